// round 13
// baseline (speedup 1.0000x reference)
#include <cuda_runtime.h>
#include <cuda_bf16.h>
#include <cstdint>
#include <math.h>

#define BATCH 4
#define T_SEQ 2048
#define NH 12
#define DMODEL 768
#define DH 64
#define M_ROWS (BATCH * T_SEQ)          // 8192
#define QKV_N (3 * DMODEL)              // 2304
#define GK DMODEL                       // GEMM K = 768
#define LDS_PAD 72                      // smem row stride in bf16 (144 B)

// ------------------------- scratch (static, allocation-free) ---------------
__device__ __nv_bfloat16 g_qkvh[(size_t)M_ROWS * QKV_N];
__device__ __nv_bfloat16 g_qkvl[(size_t)M_ROWS * QKV_N];
__device__ __nv_bfloat16 g_xh[(size_t)M_ROWS * DMODEL];
__device__ __nv_bfloat16 g_xl[(size_t)M_ROWS * DMODEL];
__device__ __nv_bfloat16 g_yh[(size_t)M_ROWS * DMODEL];
__device__ __nv_bfloat16 g_yl[(size_t)M_ROWS * DMODEL];
__device__ __nv_bfloat16 g_wah[(size_t)QKV_N * DMODEL];  // w_attn^T [2304,768]
__device__ __nv_bfloat16 g_wal[(size_t)QKV_N * DMODEL];
__device__ __nv_bfloat16 g_wph[(size_t)DMODEL * DMODEL]; // w_proj^T [768,768]
__device__ __nv_bfloat16 g_wpl[(size_t)DMODEL * DMODEL];

// ------------------------- helpers -----------------------------------------
__device__ __forceinline__ uint32_t smem_u32(const void* p) {
    uint32_t a;
    asm("{ .reg .u64 t; cvta.to.shared.u64 t, %1; cvt.u32.u64 %0, t; }" : "=r"(a) : "l"(p));
    return a;
}
__device__ __forceinline__ void cp16(uint32_t dst, const void* src) {
    asm volatile("cp.async.cg.shared.global [%0], [%1], 16;" :: "r"(dst), "l"(src));
}
#define CP_COMMIT() asm volatile("cp.async.commit_group;" ::: "memory")
#define CP_WAIT0()  asm volatile("cp.async.wait_group 0;" ::: "memory")

__device__ __forceinline__ void ldsm_x4(uint32_t& r0, uint32_t& r1,
                                        uint32_t& r2, uint32_t& r3, uint32_t addr) {
    asm volatile("ldmatrix.sync.aligned.m8n8.x4.shared.b16 {%0,%1,%2,%3}, [%4];"
                 : "=r"(r0), "=r"(r1), "=r"(r2), "=r"(r3) : "r"(addr));
}
__device__ __forceinline__ void ldsm_x4_t(uint32_t& r0, uint32_t& r1,
                                          uint32_t& r2, uint32_t& r3, uint32_t addr) {
    asm volatile("ldmatrix.sync.aligned.m8n8.x4.trans.shared.b16 {%0,%1,%2,%3}, [%4];"
                 : "=r"(r0), "=r"(r1), "=r"(r2), "=r"(r3) : "r"(addr));
}
// NOTE: not volatile — pure register op, lets ptxas schedule freely.
__device__ __forceinline__ void mma_bf16(float* c, const uint32_t* a,
                                         uint32_t b0, uint32_t b1) {
    asm("mma.sync.aligned.m16n8k16.row.col.f32.bf16.bf16.f32 "
        "{%0,%1,%2,%3}, {%4,%5,%6,%7}, {%8,%9}, {%0,%1,%2,%3};"
        : "+f"(c[0]), "+f"(c[1]), "+f"(c[2]), "+f"(c[3])
        : "r"(a[0]), "r"(a[1]), "r"(a[2]), "r"(a[3]), "r"(b0), "r"(b1));
}
__device__ __forceinline__ void pack_hl(float f0, float f1, uint32_t& h, uint32_t& l) {
    __nv_bfloat16 h0 = __float2bfloat16(f0), h1 = __float2bfloat16(f1);
    __nv_bfloat162 hh; hh.x = h0; hh.y = h1;
    h = *(uint32_t*)&hh;
    __nv_bfloat162 ll;
    ll.x = __float2bfloat16(f0 - __bfloat162float(h0));
    ll.y = __float2bfloat16(f1 - __bfloat162float(h1));
    l = *(uint32_t*)&ll;
}

// ---------------------------------------------------------------------------
// HMMA GEMM, bf16x3 (fused single-load, ILP-ordered MMAs):
//   C = Ah*Bh + Al*Bh + Ah*Bl + bias
// K-chunk 64, single-buffered cp.async, 2 CTAs/SM.
// 256 threads = 8 warps (4M x 2N), warp tile 32x64.
// Inner loop fires 16 independent MMAs between same-accumulator reuses.
// ---------------------------------------------------------------------------
#define GOAH 0
#define GOAL (128 * LDS_PAD)
#define GOBH (2 * 128 * LDS_PAD)
#define GOBL (3 * 128 * LDS_PAD)
#define GEMM_SMEM (4 * 128 * LDS_PAD * 2)    // 73728 bytes

__global__ __launch_bounds__(256, 2) void mma_gemm_kernel(
    const __nv_bfloat16* __restrict__ Ah, const __nv_bfloat16* __restrict__ Al,
    const __nv_bfloat16* __restrict__ Bh, const __nv_bfloat16* __restrict__ Bl,
    const float* __restrict__ bias, float* __restrict__ C,
    __nv_bfloat16* __restrict__ Ch, __nv_bfloat16* __restrict__ Cl, int N)
{
    extern __shared__ __nv_bfloat16 gsm[];
    const int tid  = threadIdx.x;
    const int wid  = tid >> 5;
    const int lane = tid & 31;
    const int m0 = blockIdx.y * 128;
    const int n0 = blockIdx.x * 128;
    const int warp_m = (wid >> 1) * 32;
    const int warp_n = (wid & 1) * 64;
    const uint32_t sbase = smem_u32(gsm);

    const int a_row = (lane & 15);
    const int a_coff = (lane >> 4) * 8;
    const int b_row = (lane & 7) + ((lane >> 3) & 1) * 8;
    const int b_coff = ((lane >> 4) & 1) * 8;

    float acc[2][8][4];
    #pragma unroll
    for (int mi = 0; mi < 2; mi++)
        #pragma unroll
        for (int nj = 0; nj < 8; nj++)
            #pragma unroll
            for (int q = 0; q < 4; q++) acc[mi][nj][q] = 0.0f;

    #pragma unroll 1
    for (int kc = 0; kc < GK; kc += 64) {
        __syncthreads();
        // load 4 tiles (128 rows x 64 cols each) via cp.async: 16 ops/thread
        #pragma unroll
        for (int it = 0; it < 16; it++) {
            int idx = tid + it * 256;          // 0..4095
            int tile = idx >> 10;              // 0:Ah 1:Al 2:Bh 3:Bl
            int rem = idx & 1023;
            int row = rem >> 3;                // 0..127
            int g   = rem & 7;                 // 16B granule
            const __nv_bfloat16* sp =
                (tile == 0) ? Ah : (tile == 1) ? Al : (tile == 2) ? Bh : Bl;
            int rbase = (tile < 2) ? m0 : n0;
            cp16(sbase + (uint32_t)(tile * 128 * LDS_PAD + row * LDS_PAD + g * 8) * 2,
                 sp + (size_t)(rbase + row) * GK + kc + g * 8);
        }
        CP_COMMIT();
        CP_WAIT0();
        __syncthreads();

        #pragma unroll
        for (int ks = 0; ks < 4; ks++) {
            const int k0 = ks * 16;
            uint32_t rah[2][4], ral[2][4], rb[4][4];
            #pragma unroll
            for (int mi = 0; mi < 2; mi++) {
                uint32_t ar = (warp_m + mi * 16 + a_row) * LDS_PAD + k0 + a_coff;
                ldsm_x4(rah[mi][0], rah[mi][1], rah[mi][2], rah[mi][3],
                        sbase + (GOAH + ar) * 2);
                ldsm_x4(ral[mi][0], ral[mi][1], ral[mi][2], ral[mi][3],
                        sbase + (GOAL + ar) * 2);
            }
            #pragma unroll
            for (int nb = 0; nb < 4; nb++)
                ldsm_x4(rb[nb][0], rb[nb][1], rb[nb][2], rb[nb][3],
                        sbase + (GOBH + (warp_n + nb * 16 + b_row) * LDS_PAD + k0 + b_coff) * 2);
            // 16 independent MMAs (hh), then 16 (lh): per-acc order hh->lh kept
            #pragma unroll
            for (int nb = 0; nb < 4; nb++)
                #pragma unroll
                for (int lo = 0; lo < 2; lo++)
                    #pragma unroll
                    for (int mi = 0; mi < 2; mi++)
                        mma_bf16(acc[mi][2 * nb + lo], rah[mi], rb[nb][lo], rb[nb][lo + 2]);
            #pragma unroll
            for (int nb = 0; nb < 4; nb++)
                #pragma unroll
                for (int lo = 0; lo < 2; lo++)
                    #pragma unroll
                    for (int mi = 0; mi < 2; mi++)
                        mma_bf16(acc[mi][2 * nb + lo], ral[mi], rb[nb][lo], rb[nb][lo + 2]);
            #pragma unroll
            for (int nb = 0; nb < 4; nb++)
                ldsm_x4(rb[nb][0], rb[nb][1], rb[nb][2], rb[nb][3],
                        sbase + (GOBL + (warp_n + nb * 16 + b_row) * LDS_PAD + k0 + b_coff) * 2);
            #pragma unroll
            for (int nb = 0; nb < 4; nb++)
                #pragma unroll
                for (int lo = 0; lo < 2; lo++)
                    #pragma unroll
                    for (int mi = 0; mi < 2; mi++)
                        mma_bf16(acc[mi][2 * nb + lo], rah[mi], rb[nb][lo], rb[nb][lo + 2]);
        }
    }

    const int mrow = m0 + warp_m + (lane >> 2);
    const int ncol = n0 + warp_n + (lane & 3) * 2;
    #pragma unroll
    for (int mi = 0; mi < 2; mi++) {
        #pragma unroll
        for (int nj = 0; nj < 8; nj++) {
            int r = mrow + mi * 16;
            int c = ncol + nj * 8;
            float bv0 = bias[c], bv1 = bias[c + 1];
            float v00 = acc[mi][nj][0] + bv0, v01 = acc[mi][nj][1] + bv1;
            float v10 = acc[mi][nj][2] + bv0, v11 = acc[mi][nj][3] + bv1;
            if (Cl) {
                uint32_t h0, l0, h1, l1;
                pack_hl(v00, v01, h0, l0);
                pack_hl(v10, v11, h1, l1);
                *(uint32_t*)(Ch + (size_t)r * N + c) = h0;
                *(uint32_t*)(Cl + (size_t)r * N + c) = l0;
                *(uint32_t*)(Ch + (size_t)(r + 8) * N + c) = h1;
                *(uint32_t*)(Cl + (size_t)(r + 8) * N + c) = l1;
            } else {
                *(float2*)(C + (size_t)r * N + c) = make_float2(v00, v01);
                *(float2*)(C + (size_t)(r + 8) * N + c) = make_float2(v10, v11);
            }
        }
    }
}

// ---------------------------------------------------------------------------
// HMMA flash attention (causal), bf16x3, ILP-ordered MMAs.
// Grid (T/128, B*NH), 256 threads = 8 warps x 16 Q-rows. K/V tiles 64 rows.
// ---------------------------------------------------------------------------
#define AQH 0
#define AQL (128 * LDS_PAD)
#define AKH (2 * 128 * LDS_PAD)
#define AKL (AKH + 64 * LDS_PAD)
#define AVH (AKL + 64 * LDS_PAD)
#define AVL (AVH + 64 * LDS_PAD)
#define ATTN_SMEM ((AVL + 64 * LDS_PAD) * 2)

__global__ __launch_bounds__(256, 2) void mma_attn_kernel(
    const __nv_bfloat16* __restrict__ qkvh, const __nv_bfloat16* __restrict__ qkvl,
    __nv_bfloat16* __restrict__ yh, __nv_bfloat16* __restrict__ yl)
{
    extern __shared__ __nv_bfloat16 sm[];
    const int tid = threadIdx.x;
    const int wid = tid >> 5;
    const int lane = tid & 31;
    const int qt = gridDim.x - 1 - blockIdx.x;     // heavy tiles first
    const int bh = blockIdx.y;
    const int b = bh / NH;
    const int h = bh % NH;
    const size_t base = (size_t)b * T_SEQ * QKV_N;
    const int qoff = h * DH;
    const int koff = DMODEL + h * DH;
    const int voff = 2 * DMODEL + h * DH;
    const uint32_t sbase = smem_u32(sm);

    const int a_row = (lane & 15);
    const int a_coff = (lane >> 4) * 8;
    const int b_row = (lane & 7) + ((lane >> 3) & 1) * 8;
    const int b_coff = ((lane >> 4) & 1) * 8;
    const int v_krow = ((lane >> 3) & 1) * 8 + (lane & 7);
    const int v_ncol = ((lane >> 4) & 1) * 8;

    // ---- load Q tile (hi/lo) via cp.async ----
    #pragma unroll
    for (int it = 0; it < 4; it++) {
        int idx = tid + it * 256;        // 0..1023
        int row = idx >> 3, g = idx & 7;
        size_t goff = base + (size_t)(qt * 128 + row) * QKV_N + qoff + g * 8;
        uint32_t so = (uint32_t)(row * LDS_PAD + g * 8) * 2;
        cp16(sbase + (AQH * 2) + so, qkvh + goff);
        cp16(sbase + (AQL * 2) + so, qkvl + goff);
    }
    CP_COMMIT();

    float oacc[8][4];
    #pragma unroll
    for (int nj = 0; nj < 8; nj++)
        #pragma unroll
        for (int q = 0; q < 4; q++) oacc[nj][q] = 0.0f;
    float m_a = -1e30f, m_b = -1e30f, l_a = 0.0f, l_b = 0.0f;

    const int gr_a = qt * 128 + wid * 16 + (lane >> 2);
    const int gr_b = gr_a + 8;
    const int nkt = 2 * qt + 2;

    #pragma unroll 1
    for (int kt = 0; kt < nkt; kt++) {
        __syncthreads();
        // ---- load K/V tiles (hi/lo) via cp.async ----
        #pragma unroll
        for (int it = 0; it < 8; it++) {
            int idx = tid + it * 256;     // 0..2047
            int tile = idx >> 9;          // 0:Kh 1:Kl 2:Vh 3:Vl
            int r = (idx >> 3) & 63;
            int g = idx & 7;
            const __nv_bfloat16* src = (tile & 1) ? qkvl : qkvh;
            int off = (tile < 2) ? koff : voff;
            int dsto = (tile == 0) ? AKH : (tile == 1) ? AKL : (tile == 2) ? AVH : AVL;
            cp16(sbase + (uint32_t)(dsto + r * LDS_PAD + g * 8) * 2,
                 src + base + (size_t)(kt * 64 + r) * QKV_N + off + g * 8);
        }
        CP_COMMIT();
        CP_WAIT0();
        __syncthreads();

        // ---- S = Qh*Kh + Ql*Kh + Qh*Kl (ILP-ordered) ----
        float sacc[8][4];
        #pragma unroll
        for (int nj = 0; nj < 8; nj++)
            #pragma unroll
            for (int q = 0; q < 4; q++) sacc[nj][q] = 0.0f;

        #pragma unroll
        for (int ks = 0; ks < 4; ks++) {
            const int k0 = ks * 16;
            uint32_t qh[4], ql[4], rb[4][4];
            uint32_t qr = (wid * 16 + a_row) * LDS_PAD + k0 + a_coff;
            ldsm_x4(qh[0], qh[1], qh[2], qh[3], sbase + (AQH + qr) * 2);
            ldsm_x4(ql[0], ql[1], ql[2], ql[3], sbase + (AQL + qr) * 2);
            #pragma unroll
            for (int nb = 0; nb < 4; nb++)
                ldsm_x4(rb[nb][0], rb[nb][1], rb[nb][2], rb[nb][3],
                        sbase + (AKH + (nb * 16 + b_row) * LDS_PAD + k0 + b_coff) * 2);
            #pragma unroll
            for (int nb = 0; nb < 4; nb++)
                #pragma unroll
                for (int lo = 0; lo < 2; lo++)
                    mma_bf16(sacc[2 * nb + lo], qh, rb[nb][lo], rb[nb][lo + 2]);
            #pragma unroll
            for (int nb = 0; nb < 4; nb++)
                #pragma unroll
                for (int lo = 0; lo < 2; lo++)
                    mma_bf16(sacc[2 * nb + lo], ql, rb[nb][lo], rb[nb][lo + 2]);
            #pragma unroll
            for (int nb = 0; nb < 4; nb++)
                ldsm_x4(rb[nb][0], rb[nb][1], rb[nb][2], rb[nb][3],
                        sbase + (AKL + (nb * 16 + b_row) * LDS_PAD + k0 + b_coff) * 2);
            #pragma unroll
            for (int nb = 0; nb < 4; nb++)
                #pragma unroll
                for (int lo = 0; lo < 2; lo++)
                    mma_bf16(sacc[2 * nb + lo], qh, rb[nb][lo], rb[nb][lo + 2]);
        }

        // ---- scale + causal mask ----
        const bool diag = (kt >= 2 * qt);
        #pragma unroll
        for (int nj = 0; nj < 8; nj++) {
            #pragma unroll
            for (int q = 0; q < 4; q++) sacc[nj][q] *= 0.125f;
            if (diag) {
                int gc = kt * 64 + nj * 8 + (lane & 3) * 2;
                if (gc > gr_a)     sacc[nj][0] = -1e30f;
                if (gc + 1 > gr_a) sacc[nj][1] = -1e30f;
                if (gc > gr_b)     sacc[nj][2] = -1e30f;
                if (gc + 1 > gr_b) sacc[nj][3] = -1e30f;
            }
        }

        // ---- online softmax ----
        float mx_a = -1e30f, mx_b = -1e30f;
        #pragma unroll
        for (int nj = 0; nj < 8; nj++) {
            mx_a = fmaxf(mx_a, fmaxf(sacc[nj][0], sacc[nj][1]));
            mx_b = fmaxf(mx_b, fmaxf(sacc[nj][2], sacc[nj][3]));
        }
        mx_a = fmaxf(mx_a, __shfl_xor_sync(0xffffffffu, mx_a, 1));
        mx_a = fmaxf(mx_a, __shfl_xor_sync(0xffffffffu, mx_a, 2));
        mx_b = fmaxf(mx_b, __shfl_xor_sync(0xffffffffu, mx_b, 1));
        mx_b = fmaxf(mx_b, __shfl_xor_sync(0xffffffffu, mx_b, 2));
        float mn_a = fmaxf(m_a, mx_a), mn_b = fmaxf(m_b, mx_b);
        float corr_a = __expf(m_a - mn_a), corr_b = __expf(m_b - mn_b);
        float sum_a = 0.0f, sum_b = 0.0f;
        #pragma unroll
        for (int nj = 0; nj < 8; nj++) {
            sacc[nj][0] = __expf(sacc[nj][0] - mn_a);
            sacc[nj][1] = __expf(sacc[nj][1] - mn_a);
            sacc[nj][2] = __expf(sacc[nj][2] - mn_b);
            sacc[nj][3] = __expf(sacc[nj][3] - mn_b);
            sum_a += sacc[nj][0] + sacc[nj][1];
            sum_b += sacc[nj][2] + sacc[nj][3];
        }
        sum_a += __shfl_xor_sync(0xffffffffu, sum_a, 1);
        sum_a += __shfl_xor_sync(0xffffffffu, sum_a, 2);
        sum_b += __shfl_xor_sync(0xffffffffu, sum_b, 1);
        sum_b += __shfl_xor_sync(0xffffffffu, sum_b, 2);
        l_a = l_a * corr_a + sum_a;
        l_b = l_b * corr_b + sum_b;
        m_a = mn_a; m_b = mn_b;
        #pragma unroll
        for (int nj = 0; nj < 8; nj++) {
            oacc[nj][0] *= corr_a; oacc[nj][1] *= corr_a;
            oacc[nj][2] *= corr_b; oacc[nj][3] *= corr_b;
        }

        // ---- O += (Ph+Pl) * (Vh+Vl) : PhVh + PlVh + PhVl (ILP-ordered) ----
        #pragma unroll
        for (int kb = 0; kb < 4; kb++) {
            uint32_t pa_h[4], pa_l[4], rv[4][4];
            pack_hl(sacc[2 * kb][0], sacc[2 * kb][1], pa_h[0], pa_l[0]);
            pack_hl(sacc[2 * kb][2], sacc[2 * kb][3], pa_h[1], pa_l[1]);
            pack_hl(sacc[2 * kb + 1][0], sacc[2 * kb + 1][1], pa_h[2], pa_l[2]);
            pack_hl(sacc[2 * kb + 1][2], sacc[2 * kb + 1][3], pa_h[3], pa_l[3]);
            #pragma unroll
            for (int nout = 0; nout < 4; nout++)
                ldsm_x4_t(rv[nout][0], rv[nout][1], rv[nout][2], rv[nout][3],
                          sbase + (AVH + (kb * 16 + v_krow) * LDS_PAD + nout * 16 + v_ncol) * 2);
            #pragma unroll
            for (int nout = 0; nout < 4; nout++) {
                mma_bf16(oacc[2 * nout], pa_h, rv[nout][0], rv[nout][1]);
                mma_bf16(oacc[2 * nout + 1], pa_h, rv[nout][2], rv[nout][3]);
            }
            #pragma unroll
            for (int nout = 0; nout < 4; nout++) {
                mma_bf16(oacc[2 * nout], pa_l, rv[nout][0], rv[nout][1]);
                mma_bf16(oacc[2 * nout + 1], pa_l, rv[nout][2], rv[nout][3]);
            }
            #pragma unroll
            for (int nout = 0; nout < 4; nout++)
                ldsm_x4_t(rv[nout][0], rv[nout][1], rv[nout][2], rv[nout][3],
                          sbase + (AVL + (kb * 16 + v_krow) * LDS_PAD + nout * 16 + v_ncol) * 2);
            #pragma unroll
            for (int nout = 0; nout < 4; nout++) {
                mma_bf16(oacc[2 * nout], pa_h, rv[nout][0], rv[nout][1]);
                mma_bf16(oacc[2 * nout + 1], pa_h, rv[nout][2], rv[nout][3]);
            }
        }
    }

    // ---- epilogue: y = O / l, split hi/lo ----
    const float inv_a = 1.0f / l_a;
    const float inv_b = 1.0f / l_b;
    #pragma unroll
    for (int nj = 0; nj < 8; nj++) {
        int col = h * DH + nj * 8 + (lane & 3) * 2;
        size_t ra = (size_t)(b * T_SEQ + gr_a) * DMODEL + col;
        size_t rb2 = (size_t)(b * T_SEQ + gr_b) * DMODEL + col;
        uint32_t h0, l0, h1, l1;
        pack_hl(oacc[nj][0] * inv_a, oacc[nj][1] * inv_a, h0, l0);
        pack_hl(oacc[nj][2] * inv_b, oacc[nj][3] * inv_b, h1, l1);
        *(uint32_t*)(yh + ra) = h0;
        *(uint32_t*)(yl + ra) = l0;
        *(uint32_t*)(yh + rb2) = h1;
        *(uint32_t*)(yl + rb2) = l1;
    }
}

// ---------------------------------------------------------------------------
// fp32 -> (hi, lo) bf16 split
// ---------------------------------------------------------------------------
__global__ __launch_bounds__(256) void split_kernel(
    const float* __restrict__ in, __nv_bfloat16* __restrict__ hi,
    __nv_bfloat16* __restrict__ lo, int n4)
{
    int i = blockIdx.x * blockDim.x + threadIdx.x;
    if (i >= n4) return;
    float4 v = *(const float4*)(in + (size_t)i * 4);
    __nv_bfloat16 h[4], l[4];
    float f[4] = {v.x, v.y, v.z, v.w};
    #pragma unroll
    for (int k = 0; k < 4; ++k) {
        h[k] = __float2bfloat16(f[k]);
        l[k] = __float2bfloat16(f[k] - __bfloat162float(h[k]));
    }
    *(uint2*)(hi + (size_t)i * 4) = *(uint2*)h;
    *(uint2*)(lo + (size_t)i * 4) = *(uint2*)l;
}

// ---------------------------------------------------------------------------
// W [K,N] fp32 -> W^T (hi, lo) bf16 [N,K]
// ---------------------------------------------------------------------------
__global__ __launch_bounds__(256) void split_transpose_kernel(
    const float* __restrict__ W, __nv_bfloat16* __restrict__ hiT,
    __nv_bfloat16* __restrict__ loT, int K, int N)
{
    __shared__ float tile[32][33];
    const int tx = threadIdx.x;
    const int ty = threadIdx.y;
    const int k0 = blockIdx.y * 32;
    const int n0 = blockIdx.x * 32;
    #pragma unroll
    for (int r = 0; r < 32; r += 8)
        tile[ty + r][tx] = W[(size_t)(k0 + ty + r) * N + n0 + tx];
    __syncthreads();
    #pragma unroll
    for (int r = 0; r < 32; r += 8) {
        float v = tile[tx][ty + r];
        __nv_bfloat16 h = __float2bfloat16(v);
        __nv_bfloat16 l = __float2bfloat16(v - __bfloat162float(h));
        size_t o = (size_t)(n0 + ty + r) * K + k0 + tx;
        hiT[o] = h;
        loT[o] = l;
    }
}

// ---------------------------------------------------------------------------
extern "C" void kernel_launch(void* const* d_in, const int* in_sizes, int n_in,
                              void* d_out, int out_size)
{
    const float* x      = (const float*)d_in[0];
    const float* w_attn = (const float*)d_in[1];
    const float* b_attn = (const float*)d_in[2];
    const float* w_proj = (const float*)d_in[3];
    const float* b_proj = (const float*)d_in[4];
    float* out = (float*)d_out;

    __nv_bfloat16 *qkvh, *qkvl, *xh, *xl, *yh, *yl, *wah, *wal, *wph, *wpl;
    cudaGetSymbolAddress((void**)&qkvh, g_qkvh);
    cudaGetSymbolAddress((void**)&qkvl, g_qkvl);
    cudaGetSymbolAddress((void**)&xh, g_xh);
    cudaGetSymbolAddress((void**)&xl, g_xl);
    cudaGetSymbolAddress((void**)&yh, g_yh);
    cudaGetSymbolAddress((void**)&yl, g_yl);
    cudaGetSymbolAddress((void**)&wah, g_wah);
    cudaGetSymbolAddress((void**)&wal, g_wal);
    cudaGetSymbolAddress((void**)&wph, g_wph);
    cudaGetSymbolAddress((void**)&wpl, g_wpl);

    static bool attr_set = false;
    if (!attr_set) {
        cudaFuncSetAttribute(mma_attn_kernel,
                             cudaFuncAttributeMaxDynamicSharedMemorySize, ATTN_SMEM);
        cudaFuncSetAttribute(mma_gemm_kernel,
                             cudaFuncAttributeMaxDynamicSharedMemorySize, GEMM_SMEM);
        attr_set = true;
    }

    // 0) conversions
    {
        int n4 = (M_ROWS * DMODEL) / 4;
        split_kernel<<<(n4 + 255) / 256, 256>>>(x, xh, xl, n4);
        dim3 blk(32, 8);
        split_transpose_kernel<<<dim3(QKV_N / 32, DMODEL / 32), blk>>>(w_attn, wah, wal, DMODEL, QKV_N);
        split_transpose_kernel<<<dim3(DMODEL / 32, DMODEL / 32), blk>>>(w_proj, wph, wpl, DMODEL, DMODEL);
    }
    // 1) QKV GEMM -> bf16 hi/lo qkv
    {
        dim3 grid(QKV_N / 128, M_ROWS / 128);
        mma_gemm_kernel<<<grid, 256, GEMM_SMEM>>>(xh, xl, wah, wal, b_attn,
                                                  nullptr, qkvh, qkvl, QKV_N);
    }
    // 2) causal flash attention on HMMA -> bf16 hi/lo y
    {
        dim3 grid(T_SEQ / 128, BATCH * NH);   // (16, 48)
        mma_attn_kernel<<<grid, 256, ATTN_SMEM>>>(qkvh, qkvl, yh, yl);
    }
    // 3) out projection -> fp32 out
    {
        dim3 grid(DMODEL / 128, M_ROWS / 128);
        mma_gemm_kernel<<<grid, 256, GEMM_SMEM>>>(yh, yl, wph, wpl, b_proj,
                                                  out, nullptr, nullptr, DMODEL);
    }
}

// round 14
// speedup vs baseline: 1.5646x; 1.5646x over previous
#include <cuda_runtime.h>
#include <cuda_bf16.h>
#include <cstdint>
#include <math.h>

#define BATCH 4
#define T_SEQ 2048
#define NH 12
#define DMODEL 768
#define DH 64
#define M_ROWS (BATCH * T_SEQ)          // 8192
#define QKV_N (3 * DMODEL)              // 2304
#define GK DMODEL                       // GEMM K = 768
#define LDS_PAD 72                      // smem row stride in bf16 (144 B)

// ------------------------- scratch (static, allocation-free) ---------------
__device__ __nv_bfloat16 g_qkvh[(size_t)M_ROWS * QKV_N];
__device__ __nv_bfloat16 g_qkvl[(size_t)M_ROWS * QKV_N];
__device__ __nv_bfloat16 g_xh[(size_t)M_ROWS * DMODEL];
__device__ __nv_bfloat16 g_xl[(size_t)M_ROWS * DMODEL];
__device__ __nv_bfloat16 g_yh[(size_t)M_ROWS * DMODEL];
__device__ __nv_bfloat16 g_yl[(size_t)M_ROWS * DMODEL];
__device__ __nv_bfloat16 g_wah[(size_t)QKV_N * DMODEL];  // w_attn^T [2304,768]
__device__ __nv_bfloat16 g_wal[(size_t)QKV_N * DMODEL];
__device__ __nv_bfloat16 g_wph[(size_t)DMODEL * DMODEL]; // w_proj^T [768,768]
__device__ __nv_bfloat16 g_wpl[(size_t)DMODEL * DMODEL];

// ------------------------- helpers -----------------------------------------
__device__ __forceinline__ uint32_t smem_u32(const void* p) {
    uint32_t a;
    asm("{ .reg .u64 t; cvta.to.shared.u64 t, %1; cvt.u32.u64 %0, t; }" : "=r"(a) : "l"(p));
    return a;
}
__device__ __forceinline__ void cp16(uint32_t dst, const void* src) {
    asm volatile("cp.async.cg.shared.global [%0], [%1], 16;" :: "r"(dst), "l"(src));
}
#define CP_COMMIT() asm volatile("cp.async.commit_group;" ::: "memory")
#define CP_WAIT0()  asm volatile("cp.async.wait_group 0;" ::: "memory")

__device__ __forceinline__ void ldsm_x4(uint32_t& r0, uint32_t& r1,
                                        uint32_t& r2, uint32_t& r3, uint32_t addr) {
    asm volatile("ldmatrix.sync.aligned.m8n8.x4.shared.b16 {%0,%1,%2,%3}, [%4];"
                 : "=r"(r0), "=r"(r1), "=r"(r2), "=r"(r3) : "r"(addr));
}
__device__ __forceinline__ void ldsm_x4_t(uint32_t& r0, uint32_t& r1,
                                          uint32_t& r2, uint32_t& r3, uint32_t addr) {
    asm volatile("ldmatrix.sync.aligned.m8n8.x4.trans.shared.b16 {%0,%1,%2,%3}, [%4];"
                 : "=r"(r0), "=r"(r1), "=r"(r2), "=r"(r3) : "r"(addr));
}
__device__ __forceinline__ void mma_bf16(float* c, const uint32_t* a,
                                         uint32_t b0, uint32_t b1) {
    asm volatile(
        "mma.sync.aligned.m16n8k16.row.col.f32.bf16.bf16.f32 "
        "{%0,%1,%2,%3}, {%4,%5,%6,%7}, {%8,%9}, {%0,%1,%2,%3};"
        : "+f"(c[0]), "+f"(c[1]), "+f"(c[2]), "+f"(c[3])
        : "r"(a[0]), "r"(a[1]), "r"(a[2]), "r"(a[3]), "r"(b0), "r"(b1));
}
__device__ __forceinline__ void pack_hl(float f0, float f1, uint32_t& h, uint32_t& l) {
    __nv_bfloat16 h0 = __float2bfloat16(f0), h1 = __float2bfloat16(f1);
    __nv_bfloat162 hh; hh.x = h0; hh.y = h1;
    h = *(uint32_t*)&hh;
    __nv_bfloat162 ll;
    ll.x = __float2bfloat16(f0 - __bfloat162float(h0));
    ll.y = __float2bfloat16(f1 - __bfloat162float(h1));
    l = *(uint32_t*)&ll;
}

// ---------------------------------------------------------------------------
// HMMA GEMM, bf16x3 (fused single-load): C = Ah*Bh + Al*Bh + Ah*Bl + bias
// Per K-chunk (64): load Ah|Al|Bh|Bl tiles once via cp.async, run all 3 terms.
// Register-neutral ILP order: per nb, 4 independent hh MMAs, then 4 lh, then
// (after Bl ldsm) 4 hl. Per-accumulator order hh->lh->hl preserved.
// ---------------------------------------------------------------------------
#define GOAH 0
#define GOAL (128 * LDS_PAD)
#define GOBH (2 * 128 * LDS_PAD)
#define GOBL (3 * 128 * LDS_PAD)
#define GEMM_SMEM (4 * 128 * LDS_PAD * 2)    // 73728 bytes

__global__ __launch_bounds__(256, 2) void mma_gemm_kernel(
    const __nv_bfloat16* __restrict__ Ah, const __nv_bfloat16* __restrict__ Al,
    const __nv_bfloat16* __restrict__ Bh, const __nv_bfloat16* __restrict__ Bl,
    const float* __restrict__ bias, float* __restrict__ C,
    __nv_bfloat16* __restrict__ Ch, __nv_bfloat16* __restrict__ Cl, int N)
{
    extern __shared__ __nv_bfloat16 gsm[];
    const int tid  = threadIdx.x;
    const int wid  = tid >> 5;
    const int lane = tid & 31;
    const int m0 = blockIdx.y * 128;
    const int n0 = blockIdx.x * 128;
    const int warp_m = (wid >> 1) * 32;
    const int warp_n = (wid & 1) * 64;
    const uint32_t sbase = smem_u32(gsm);

    const int a_row = (lane & 15);
    const int a_coff = (lane >> 4) * 8;
    const int b_row = (lane & 7) + ((lane >> 3) & 1) * 8;
    const int b_coff = ((lane >> 4) & 1) * 8;

    float acc[2][8][4];
    #pragma unroll
    for (int mi = 0; mi < 2; mi++)
        #pragma unroll
        for (int nj = 0; nj < 8; nj++)
            #pragma unroll
            for (int q = 0; q < 4; q++) acc[mi][nj][q] = 0.0f;

    #pragma unroll 1
    for (int kc = 0; kc < GK; kc += 64) {
        __syncthreads();
        // load 4 tiles (128 rows x 64 cols each) via cp.async: 16 ops/thread
        #pragma unroll
        for (int it = 0; it < 16; it++) {
            int idx = tid + it * 256;          // 0..4095
            int tile = idx >> 10;              // 0:Ah 1:Al 2:Bh 3:Bl
            int rem = idx & 1023;
            int row = rem >> 3;                // 0..127
            int g   = rem & 7;                 // 16B granule
            const __nv_bfloat16* sp =
                (tile == 0) ? Ah : (tile == 1) ? Al : (tile == 2) ? Bh : Bl;
            int rbase = (tile < 2) ? m0 : n0;
            cp16(sbase + (uint32_t)(tile * 128 * LDS_PAD + row * LDS_PAD + g * 8) * 2,
                 sp + (size_t)(rbase + row) * GK + kc + g * 8);
        }
        CP_COMMIT();
        CP_WAIT0();
        __syncthreads();

        #pragma unroll
        for (int ks = 0; ks < 4; ks++) {
            const int k0 = ks * 16;
            uint32_t rah[2][4], ral[2][4];
            #pragma unroll
            for (int mi = 0; mi < 2; mi++) {
                uint32_t ar = (warp_m + mi * 16 + a_row) * LDS_PAD + k0 + a_coff;
                ldsm_x4(rah[mi][0], rah[mi][1], rah[mi][2], rah[mi][3],
                        sbase + (GOAH + ar) * 2);
                ldsm_x4(ral[mi][0], ral[mi][1], ral[mi][2], ral[mi][3],
                        sbase + (GOAL + ar) * 2);
            }
            #pragma unroll
            for (int nb = 0; nb < 4; nb++) {
                uint32_t br = (warp_n + nb * 16 + b_row) * LDS_PAD + k0 + b_coff;
                uint32_t rb[4];
                ldsm_x4(rb[0], rb[1], rb[2], rb[3], sbase + (GOBH + br) * 2);
                // 4 independent hh MMAs
                #pragma unroll
                for (int lo = 0; lo < 2; lo++)
                    #pragma unroll
                    for (int mi = 0; mi < 2; mi++)
                        mma_bf16(acc[mi][2 * nb + lo], rah[mi], rb[lo], rb[lo + 2]);
                // 4 independent lh MMAs
                #pragma unroll
                for (int lo = 0; lo < 2; lo++)
                    #pragma unroll
                    for (int mi = 0; mi < 2; mi++)
                        mma_bf16(acc[mi][2 * nb + lo], ral[mi], rb[lo], rb[lo + 2]);
                ldsm_x4(rb[0], rb[1], rb[2], rb[3], sbase + (GOBL + br) * 2);
                // 4 independent hl MMAs
                #pragma unroll
                for (int lo = 0; lo < 2; lo++)
                    #pragma unroll
                    for (int mi = 0; mi < 2; mi++)
                        mma_bf16(acc[mi][2 * nb + lo], rah[mi], rb[lo], rb[lo + 2]);
            }
        }
    }

    const int mrow = m0 + warp_m + (lane >> 2);
    const int ncol = n0 + warp_n + (lane & 3) * 2;
    #pragma unroll
    for (int mi = 0; mi < 2; mi++) {
        #pragma unroll
        for (int nj = 0; nj < 8; nj++) {
            int r = mrow + mi * 16;
            int c = ncol + nj * 8;
            float bv0 = bias[c], bv1 = bias[c + 1];
            float v00 = acc[mi][nj][0] + bv0, v01 = acc[mi][nj][1] + bv1;
            float v10 = acc[mi][nj][2] + bv0, v11 = acc[mi][nj][3] + bv1;
            if (Cl) {
                uint32_t h0, l0, h1, l1;
                pack_hl(v00, v01, h0, l0);
                pack_hl(v10, v11, h1, l1);
                *(uint32_t*)(Ch + (size_t)r * N + c) = h0;
                *(uint32_t*)(Cl + (size_t)r * N + c) = l0;
                *(uint32_t*)(Ch + (size_t)(r + 8) * N + c) = h1;
                *(uint32_t*)(Cl + (size_t)(r + 8) * N + c) = l1;
            } else {
                *(float2*)(C + (size_t)r * N + c) = make_float2(v00, v01);
                *(float2*)(C + (size_t)(r + 8) * N + c) = make_float2(v10, v11);
            }
        }
    }
}

// ---------------------------------------------------------------------------
// HMMA flash attention (causal), bf16x3 S and PV, fp32 softmax/accum.
// Grid (T/128, B*NH), 256 threads = 8 warps x 16 Q-rows. K/V tiles 64 rows.
// Register-neutral ILP order inside each fragment group.
// ---------------------------------------------------------------------------
#define AQH 0
#define AQL (128 * LDS_PAD)
#define AKH (2 * 128 * LDS_PAD)
#define AKL (AKH + 64 * LDS_PAD)
#define AVH (AKL + 64 * LDS_PAD)
#define AVL (AVH + 64 * LDS_PAD)
#define ATTN_SMEM ((AVL + 64 * LDS_PAD) * 2)

__global__ __launch_bounds__(256, 2) void mma_attn_kernel(
    const __nv_bfloat16* __restrict__ qkvh, const __nv_bfloat16* __restrict__ qkvl,
    __nv_bfloat16* __restrict__ yh, __nv_bfloat16* __restrict__ yl)
{
    extern __shared__ __nv_bfloat16 sm[];
    const int tid = threadIdx.x;
    const int wid = tid >> 5;
    const int lane = tid & 31;
    const int qt = gridDim.x - 1 - blockIdx.x;     // heavy tiles first
    const int bh = blockIdx.y;
    const int b = bh / NH;
    const int h = bh % NH;
    const size_t base = (size_t)b * T_SEQ * QKV_N;
    const int qoff = h * DH;
    const int koff = DMODEL + h * DH;
    const int voff = 2 * DMODEL + h * DH;
    const uint32_t sbase = smem_u32(sm);

    const int a_row = (lane & 15);
    const int a_coff = (lane >> 4) * 8;
    const int b_row = (lane & 7) + ((lane >> 3) & 1) * 8;
    const int b_coff = ((lane >> 4) & 1) * 8;
    const int v_krow = ((lane >> 3) & 1) * 8 + (lane & 7);
    const int v_ncol = ((lane >> 4) & 1) * 8;

    // ---- load Q tile (hi/lo) via cp.async ----
    #pragma unroll
    for (int it = 0; it < 4; it++) {
        int idx = tid + it * 256;        // 0..1023
        int row = idx >> 3, g = idx & 7;
        size_t goff = base + (size_t)(qt * 128 + row) * QKV_N + qoff + g * 8;
        uint32_t so = (uint32_t)(row * LDS_PAD + g * 8) * 2;
        cp16(sbase + (AQH * 2) + so, qkvh + goff);
        cp16(sbase + (AQL * 2) + so, qkvl + goff);
    }
    CP_COMMIT();

    float oacc[8][4];
    #pragma unroll
    for (int nj = 0; nj < 8; nj++)
        #pragma unroll
        for (int q = 0; q < 4; q++) oacc[nj][q] = 0.0f;
    float m_a = -1e30f, m_b = -1e30f, l_a = 0.0f, l_b = 0.0f;

    const int gr_a = qt * 128 + wid * 16 + (lane >> 2);
    const int gr_b = gr_a + 8;
    const int nkt = 2 * qt + 2;

    #pragma unroll 1
    for (int kt = 0; kt < nkt; kt++) {
        __syncthreads();
        // ---- load K/V tiles (hi/lo) via cp.async ----
        #pragma unroll
        for (int it = 0; it < 8; it++) {
            int idx = tid + it * 256;     // 0..2047
            int tile = idx >> 9;          // 0:Kh 1:Kl 2:Vh 3:Vl
            int r = (idx >> 3) & 63;
            int g = idx & 7;
            const __nv_bfloat16* src = (tile & 1) ? qkvl : qkvh;
            int off = (tile < 2) ? koff : voff;
            int dsto = (tile == 0) ? AKH : (tile == 1) ? AKL : (tile == 2) ? AVH : AVL;
            cp16(sbase + (uint32_t)(dsto + r * LDS_PAD + g * 8) * 2,
                 src + base + (size_t)(kt * 64 + r) * QKV_N + off + g * 8);
        }
        CP_COMMIT();
        CP_WAIT0();
        __syncthreads();

        // ---- S = Qh*Kh + Ql*Kh + Qh*Kl ----
        float sacc[8][4];
        #pragma unroll
        for (int nj = 0; nj < 8; nj++)
            #pragma unroll
            for (int q = 0; q < 4; q++) sacc[nj][q] = 0.0f;

        #pragma unroll
        for (int ks = 0; ks < 4; ks++) {
            const int k0 = ks * 16;
            uint32_t qh[4], ql[4];
            ldsm_x4(qh[0], qh[1], qh[2], qh[3],
                    sbase + (AQH + (wid * 16 + a_row) * LDS_PAD + k0 + a_coff) * 2);
            ldsm_x4(ql[0], ql[1], ql[2], ql[3],
                    sbase + (AQL + (wid * 16 + a_row) * LDS_PAD + k0 + a_coff) * 2);
            #pragma unroll
            for (int nb = 0; nb < 4; nb++) {
                uint32_t br = (nb * 16 + b_row) * LDS_PAD + k0 + b_coff;
                uint32_t rb[4];
                ldsm_x4(rb[0], rb[1], rb[2], rb[3], sbase + (AKH + br) * 2);
                // 2 independent hh, then 2 lh (per-acc order preserved)
                #pragma unroll
                for (int lo = 0; lo < 2; lo++)
                    mma_bf16(sacc[2 * nb + lo], qh, rb[lo], rb[lo + 2]);
                #pragma unroll
                for (int lo = 0; lo < 2; lo++)
                    mma_bf16(sacc[2 * nb + lo], ql, rb[lo], rb[lo + 2]);
                ldsm_x4(rb[0], rb[1], rb[2], rb[3], sbase + (AKL + br) * 2);
                #pragma unroll
                for (int lo = 0; lo < 2; lo++)
                    mma_bf16(sacc[2 * nb + lo], qh, rb[lo], rb[lo + 2]);
            }
        }

        // ---- scale + causal mask ----
        const bool diag = (kt >= 2 * qt);
        #pragma unroll
        for (int nj = 0; nj < 8; nj++) {
            #pragma unroll
            for (int q = 0; q < 4; q++) sacc[nj][q] *= 0.125f;
            if (diag) {
                int gc = kt * 64 + nj * 8 + (lane & 3) * 2;
                if (gc > gr_a)     sacc[nj][0] = -1e30f;
                if (gc + 1 > gr_a) sacc[nj][1] = -1e30f;
                if (gc > gr_b)     sacc[nj][2] = -1e30f;
                if (gc + 1 > gr_b) sacc[nj][3] = -1e30f;
            }
        }

        // ---- online softmax ----
        float mx_a = -1e30f, mx_b = -1e30f;
        #pragma unroll
        for (int nj = 0; nj < 8; nj++) {
            mx_a = fmaxf(mx_a, fmaxf(sacc[nj][0], sacc[nj][1]));
            mx_b = fmaxf(mx_b, fmaxf(sacc[nj][2], sacc[nj][3]));
        }
        mx_a = fmaxf(mx_a, __shfl_xor_sync(0xffffffffu, mx_a, 1));
        mx_a = fmaxf(mx_a, __shfl_xor_sync(0xffffffffu, mx_a, 2));
        mx_b = fmaxf(mx_b, __shfl_xor_sync(0xffffffffu, mx_b, 1));
        mx_b = fmaxf(mx_b, __shfl_xor_sync(0xffffffffu, mx_b, 2));
        float mn_a = fmaxf(m_a, mx_a), mn_b = fmaxf(m_b, mx_b);
        float corr_a = __expf(m_a - mn_a), corr_b = __expf(m_b - mn_b);
        float sum_a = 0.0f, sum_b = 0.0f;
        #pragma unroll
        for (int nj = 0; nj < 8; nj++) {
            sacc[nj][0] = __expf(sacc[nj][0] - mn_a);
            sacc[nj][1] = __expf(sacc[nj][1] - mn_a);
            sacc[nj][2] = __expf(sacc[nj][2] - mn_b);
            sacc[nj][3] = __expf(sacc[nj][3] - mn_b);
            sum_a += sacc[nj][0] + sacc[nj][1];
            sum_b += sacc[nj][2] + sacc[nj][3];
        }
        sum_a += __shfl_xor_sync(0xffffffffu, sum_a, 1);
        sum_a += __shfl_xor_sync(0xffffffffu, sum_a, 2);
        sum_b += __shfl_xor_sync(0xffffffffu, sum_b, 1);
        sum_b += __shfl_xor_sync(0xffffffffu, sum_b, 2);
        l_a = l_a * corr_a + sum_a;
        l_b = l_b * corr_b + sum_b;
        m_a = mn_a; m_b = mn_b;
        #pragma unroll
        for (int nj = 0; nj < 8; nj++) {
            oacc[nj][0] *= corr_a; oacc[nj][1] *= corr_a;
            oacc[nj][2] *= corr_b; oacc[nj][3] *= corr_b;
        }

        // ---- O += (Ph+Pl) * (Vh+Vl) : PhVh + PlVh + PhVl ----
        #pragma unroll
        for (int kb = 0; kb < 4; kb++) {
            uint32_t pa_h[4], pa_l[4];
            pack_hl(sacc[2 * kb][0], sacc[2 * kb][1], pa_h[0], pa_l[0]);
            pack_hl(sacc[2 * kb][2], sacc[2 * kb][3], pa_h[1], pa_l[1]);
            pack_hl(sacc[2 * kb + 1][0], sacc[2 * kb + 1][1], pa_h[2], pa_l[2]);
            pack_hl(sacc[2 * kb + 1][2], sacc[2 * kb + 1][3], pa_h[3], pa_l[3]);
            #pragma unroll
            for (int nout = 0; nout < 4; nout++) {
                uint32_t rv[4];
                ldsm_x4_t(rv[0], rv[1], rv[2], rv[3],
                          sbase + (AVH + (kb * 16 + v_krow) * LDS_PAD + nout * 16 + v_ncol) * 2);
                // 2 independent pa_h, then 2 pa_l (per-acc order preserved)
                mma_bf16(oacc[2 * nout], pa_h, rv[0], rv[1]);
                mma_bf16(oacc[2 * nout + 1], pa_h, rv[2], rv[3]);
                mma_bf16(oacc[2 * nout], pa_l, rv[0], rv[1]);
                mma_bf16(oacc[2 * nout + 1], pa_l, rv[2], rv[3]);
                ldsm_x4_t(rv[0], rv[1], rv[2], rv[3],
                          sbase + (AVL + (kb * 16 + v_krow) * LDS_PAD + nout * 16 + v_ncol) * 2);
                mma_bf16(oacc[2 * nout], pa_h, rv[0], rv[1]);
                mma_bf16(oacc[2 * nout + 1], pa_h, rv[2], rv[3]);
            }
        }
    }

    // ---- epilogue: y = O / l, split hi/lo ----
    const float inv_a = 1.0f / l_a;
    const float inv_b = 1.0f / l_b;
    #pragma unroll
    for (int nj = 0; nj < 8; nj++) {
        int col = h * DH + nj * 8 + (lane & 3) * 2;
        size_t ra = (size_t)(b * T_SEQ + gr_a) * DMODEL + col;
        size_t rb2 = (size_t)(b * T_SEQ + gr_b) * DMODEL + col;
        uint32_t h0, l0, h1, l1;
        pack_hl(oacc[nj][0] * inv_a, oacc[nj][1] * inv_a, h0, l0);
        pack_hl(oacc[nj][2] * inv_b, oacc[nj][3] * inv_b, h1, l1);
        *(uint32_t*)(yh + ra) = h0;
        *(uint32_t*)(yl + ra) = l0;
        *(uint32_t*)(yh + rb2) = h1;
        *(uint32_t*)(yl + rb2) = l1;
    }
}

// ---------------------------------------------------------------------------
// fp32 -> (hi, lo) bf16 split
// ---------------------------------------------------------------------------
__global__ __launch_bounds__(256) void split_kernel(
    const float* __restrict__ in, __nv_bfloat16* __restrict__ hi,
    __nv_bfloat16* __restrict__ lo, int n4)
{
    int i = blockIdx.x * blockDim.x + threadIdx.x;
    if (i >= n4) return;
    float4 v = *(const float4*)(in + (size_t)i * 4);
    __nv_bfloat16 h[4], l[4];
    float f[4] = {v.x, v.y, v.z, v.w};
    #pragma unroll
    for (int k = 0; k < 4; ++k) {
        h[k] = __float2bfloat16(f[k]);
        l[k] = __float2bfloat16(f[k] - __bfloat162float(h[k]));
    }
    *(uint2*)(hi + (size_t)i * 4) = *(uint2*)h;
    *(uint2*)(lo + (size_t)i * 4) = *(uint2*)l;
}

// ---------------------------------------------------------------------------
// W [K,N] fp32 -> W^T (hi, lo) bf16 [N,K]
// ---------------------------------------------------------------------------
__global__ __launch_bounds__(256) void split_transpose_kernel(
    const float* __restrict__ W, __nv_bfloat16* __restrict__ hiT,
    __nv_bfloat16* __restrict__ loT, int K, int N)
{
    __shared__ float tile[32][33];
    const int tx = threadIdx.x;
    const int ty = threadIdx.y;
    const int k0 = blockIdx.y * 32;
    const int n0 = blockIdx.x * 32;
    #pragma unroll
    for (int r = 0; r < 32; r += 8)
        tile[ty + r][tx] = W[(size_t)(k0 + ty + r) * N + n0 + tx];
    __syncthreads();
    #pragma unroll
    for (int r = 0; r < 32; r += 8) {
        float v = tile[tx][ty + r];
        __nv_bfloat16 h = __float2bfloat16(v);
        __nv_bfloat16 l = __float2bfloat16(v - __bfloat162float(h));
        size_t o = (size_t)(n0 + ty + r) * K + k0 + tx;
        hiT[o] = h;
        loT[o] = l;
    }
}

// ---------------------------------------------------------------------------
extern "C" void kernel_launch(void* const* d_in, const int* in_sizes, int n_in,
                              void* d_out, int out_size)
{
    const float* x      = (const float*)d_in[0];
    const float* w_attn = (const float*)d_in[1];
    const float* b_attn = (const float*)d_in[2];
    const float* w_proj = (const float*)d_in[3];
    const float* b_proj = (const float*)d_in[4];
    float* out = (float*)d_out;

    __nv_bfloat16 *qkvh, *qkvl, *xh, *xl, *yh, *yl, *wah, *wal, *wph, *wpl;
    cudaGetSymbolAddress((void**)&qkvh, g_qkvh);
    cudaGetSymbolAddress((void**)&qkvl, g_qkvl);
    cudaGetSymbolAddress((void**)&xh, g_xh);
    cudaGetSymbolAddress((void**)&xl, g_xl);
    cudaGetSymbolAddress((void**)&yh, g_yh);
    cudaGetSymbolAddress((void**)&yl, g_yl);
    cudaGetSymbolAddress((void**)&wah, g_wah);
    cudaGetSymbolAddress((void**)&wal, g_wal);
    cudaGetSymbolAddress((void**)&wph, g_wph);
    cudaGetSymbolAddress((void**)&wpl, g_wpl);

    static bool attr_set = false;
    if (!attr_set) {
        cudaFuncSetAttribute(mma_attn_kernel,
                             cudaFuncAttributeMaxDynamicSharedMemorySize, ATTN_SMEM);
        cudaFuncSetAttribute(mma_gemm_kernel,
                             cudaFuncAttributeMaxDynamicSharedMemorySize, GEMM_SMEM);
        attr_set = true;
    }

    // 0) conversions
    {
        int n4 = (M_ROWS * DMODEL) / 4;
        split_kernel<<<(n4 + 255) / 256, 256>>>(x, xh, xl, n4);
        dim3 blk(32, 8);
        split_transpose_kernel<<<dim3(QKV_N / 32, DMODEL / 32), blk>>>(w_attn, wah, wal, DMODEL, QKV_N);
        split_transpose_kernel<<<dim3(DMODEL / 32, DMODEL / 32), blk>>>(w_proj, wph, wpl, DMODEL, DMODEL);
    }
    // 1) QKV GEMM -> bf16 hi/lo qkv
    {
        dim3 grid(QKV_N / 128, M_ROWS / 128);
        mma_gemm_kernel<<<grid, 256, GEMM_SMEM>>>(xh, xl, wah, wal, b_attn,
                                                  nullptr, qkvh, qkvl, QKV_N);
    }
    // 2) causal flash attention on HMMA -> bf16 hi/lo y
    {
        dim3 grid(T_SEQ / 128, BATCH * NH);   // (16, 48)
        mma_attn_kernel<<<grid, 256, ATTN_SMEM>>>(qkvh, qkvl, yh, yl);
    }
    // 3) out projection -> fp32 out
    {
        dim3 grid(DMODEL / 128, M_ROWS / 128);
        mma_gemm_kernel<<<grid, 256, GEMM_SMEM>>>(yh, yl, wph, wpl, b_proj,
                                                  out, nullptr, nullptr, DMODEL);
    }
}

// round 15
// speedup vs baseline: 1.8353x; 1.1730x over previous
#include <cuda_runtime.h>
#include <cuda_bf16.h>
#include <cuda_fp16.h>
#include <cstdint>
#include <math.h>

#define BATCH 4
#define T_SEQ 2048
#define NH 12
#define DMODEL 768
#define DH 64
#define M_ROWS (BATCH * T_SEQ)          // 8192
#define QKV_N (3 * DMODEL)              // 2304
#define GK DMODEL                       // GEMM K = 768
#define LDS_PAD 72                      // smem row stride in 16-bit elems (144 B)

// ------------------------- scratch (static, allocation-free) ---------------
__device__ __nv_bfloat16 g_qkvh[(size_t)M_ROWS * QKV_N];
__device__ __nv_bfloat16 g_qkvl[(size_t)M_ROWS * QKV_N];
__device__ __half g_xh[(size_t)M_ROWS * DMODEL];
__device__ __half g_xl[(size_t)M_ROWS * DMODEL];
__device__ __half g_yh[(size_t)M_ROWS * DMODEL];
__device__ __half g_yl[(size_t)M_ROWS * DMODEL];
__device__ __half g_wah[(size_t)QKV_N * DMODEL];   // fl16(w_attn^T) [2304,768]
__device__ __half g_wph[(size_t)DMODEL * DMODEL];  // fl16(w_proj^T) [768,768]

// ------------------------- helpers -----------------------------------------
__device__ __forceinline__ uint32_t smem_u32(const void* p) {
    uint32_t a;
    asm("{ .reg .u64 t; cvta.to.shared.u64 t, %1; cvt.u32.u64 %0, t; }" : "=r"(a) : "l"(p));
    return a;
}
__device__ __forceinline__ void cp16(uint32_t dst, const void* src) {
    asm volatile("cp.async.cg.shared.global [%0], [%1], 16;" :: "r"(dst), "l"(src));
}
#define CP_COMMIT() asm volatile("cp.async.commit_group;" ::: "memory")
#define CP_WAIT0()  asm volatile("cp.async.wait_group 0;" ::: "memory")

__device__ __forceinline__ void ldsm_x4(uint32_t& r0, uint32_t& r1,
                                        uint32_t& r2, uint32_t& r3, uint32_t addr) {
    asm volatile("ldmatrix.sync.aligned.m8n8.x4.shared.b16 {%0,%1,%2,%3}, [%4];"
                 : "=r"(r0), "=r"(r1), "=r"(r2), "=r"(r3) : "r"(addr));
}
__device__ __forceinline__ void ldsm_x4_t(uint32_t& r0, uint32_t& r1,
                                          uint32_t& r2, uint32_t& r3, uint32_t addr) {
    asm volatile("ldmatrix.sync.aligned.m8n8.x4.trans.shared.b16 {%0,%1,%2,%3}, [%4];"
                 : "=r"(r0), "=r"(r1), "=r"(r2), "=r"(r3) : "r"(addr));
}
__device__ __forceinline__ void mma_bf16(float* c, const uint32_t* a,
                                         uint32_t b0, uint32_t b1) {
    asm volatile(
        "mma.sync.aligned.m16n8k16.row.col.f32.bf16.bf16.f32 "
        "{%0,%1,%2,%3}, {%4,%5,%6,%7}, {%8,%9}, {%0,%1,%2,%3};"
        : "+f"(c[0]), "+f"(c[1]), "+f"(c[2]), "+f"(c[3])
        : "r"(a[0]), "r"(a[1]), "r"(a[2]), "r"(a[3]), "r"(b0), "r"(b1));
}
__device__ __forceinline__ void mma_f16(float* c, const uint32_t* a,
                                        uint32_t b0, uint32_t b1) {
    asm volatile(
        "mma.sync.aligned.m16n8k16.row.col.f32.f16.f16.f32 "
        "{%0,%1,%2,%3}, {%4,%5,%6,%7}, {%8,%9}, {%0,%1,%2,%3};"
        : "+f"(c[0]), "+f"(c[1]), "+f"(c[2]), "+f"(c[3])
        : "r"(a[0]), "r"(a[1]), "r"(a[2]), "r"(a[3]), "r"(b0), "r"(b1));
}
__device__ __forceinline__ void pack_hl(float f0, float f1, uint32_t& h, uint32_t& l) {
    __nv_bfloat16 h0 = __float2bfloat16(f0), h1 = __float2bfloat16(f1);
    __nv_bfloat162 hh; hh.x = h0; hh.y = h1;
    h = *(uint32_t*)&hh;
    __nv_bfloat162 ll;
    ll.x = __float2bfloat16(f0 - __bfloat162float(h0));
    ll.y = __float2bfloat16(f1 - __bfloat162float(h1));
    l = *(uint32_t*)&ll;
}
__device__ __forceinline__ void pack_hl_f16(float f0, float f1, uint32_t& h, uint32_t& l) {
    __half h0 = __float2half_rn(f0), h1 = __float2half_rn(f1);
    __half2 hh = __halves2half2(h0, h1);
    h = *(uint32_t*)&hh;
    __half2 ll = __halves2half2(__float2half_rn(f0 - __half2float(h0)),
                                __float2half_rn(f1 - __half2float(h1)));
    l = *(uint32_t*)&ll;
}

// ---------------------------------------------------------------------------
// HMMA GEMM, fp16 2-term: C = (Ah + Al) * Bh + bias  ==  A * fl16(B) + bias
// Per K-chunk (64): load Ah|Al|Bh tiles once via cp.async. 32 MMAs per ks.
// 256 threads = 8 warps (4M x 2N), warp tile 32x64, 2 CTAs/SM.
// ---------------------------------------------------------------------------
#define GOAH 0
#define GOAL (128 * LDS_PAD)
#define GOBH (2 * 128 * LDS_PAD)
#define GEMM_SMEM (3 * 128 * LDS_PAD * 2)    // 55296 bytes

__global__ __launch_bounds__(256, 2) void mma_gemm_kernel(
    const __half* __restrict__ Ah, const __half* __restrict__ Al,
    const __half* __restrict__ Bh,
    const float* __restrict__ bias, float* __restrict__ C,
    __nv_bfloat16* __restrict__ Ch, __nv_bfloat16* __restrict__ Cl, int N)
{
    extern __shared__ __half gsm[];
    const int tid  = threadIdx.x;
    const int wid  = tid >> 5;
    const int lane = tid & 31;
    const int m0 = blockIdx.y * 128;
    const int n0 = blockIdx.x * 128;
    const int warp_m = (wid >> 1) * 32;
    const int warp_n = (wid & 1) * 64;
    const uint32_t sbase = smem_u32(gsm);

    const int a_row = (lane & 15);
    const int a_coff = (lane >> 4) * 8;
    const int b_row = (lane & 7) + ((lane >> 3) & 1) * 8;
    const int b_coff = ((lane >> 4) & 1) * 8;

    float acc[2][8][4];
    #pragma unroll
    for (int mi = 0; mi < 2; mi++)
        #pragma unroll
        for (int nj = 0; nj < 8; nj++)
            #pragma unroll
            for (int q = 0; q < 4; q++) acc[mi][nj][q] = 0.0f;

    #pragma unroll 1
    for (int kc = 0; kc < GK; kc += 64) {
        __syncthreads();
        // load 3 tiles (128 rows x 64 halves each): 3072 granules, 12/thread
        #pragma unroll
        for (int it = 0; it < 12; it++) {
            int idx = tid + it * 256;          // 0..3071
            int tile = idx >> 10;              // 0:Ah 1:Al 2:Bh
            int rem = idx & 1023;
            int row = rem >> 3;                // 0..127
            int g   = rem & 7;                 // 16B granule
            const __half* sp = (tile == 0) ? Ah : (tile == 1) ? Al : Bh;
            int rbase = (tile < 2) ? m0 : n0;
            cp16(sbase + (uint32_t)(tile * 128 * LDS_PAD + row * LDS_PAD + g * 8) * 2,
                 sp + (size_t)(rbase + row) * GK + kc + g * 8);
        }
        CP_COMMIT();
        CP_WAIT0();
        __syncthreads();

        #pragma unroll
        for (int ks = 0; ks < 4; ks++) {
            const int k0 = ks * 16;
            uint32_t rah[2][4], ral[2][4];
            #pragma unroll
            for (int mi = 0; mi < 2; mi++) {
                uint32_t ar = (warp_m + mi * 16 + a_row) * LDS_PAD + k0 + a_coff;
                ldsm_x4(rah[mi][0], rah[mi][1], rah[mi][2], rah[mi][3],
                        sbase + (GOAH + ar) * 2);
                ldsm_x4(ral[mi][0], ral[mi][1], ral[mi][2], ral[mi][3],
                        sbase + (GOAL + ar) * 2);
            }
            #pragma unroll
            for (int nb = 0; nb < 4; nb++) {
                uint32_t br = (warp_n + nb * 16 + b_row) * LDS_PAD + k0 + b_coff;
                uint32_t rb[4];
                ldsm_x4(rb[0], rb[1], rb[2], rb[3], sbase + (GOBH + br) * 2);
                // 4 independent hh MMAs, then 4 lh (per-acc order preserved)
                #pragma unroll
                for (int lo = 0; lo < 2; lo++)
                    #pragma unroll
                    for (int mi = 0; mi < 2; mi++)
                        mma_f16(acc[mi][2 * nb + lo], rah[mi], rb[lo], rb[lo + 2]);
                #pragma unroll
                for (int lo = 0; lo < 2; lo++)
                    #pragma unroll
                    for (int mi = 0; mi < 2; mi++)
                        mma_f16(acc[mi][2 * nb + lo], ral[mi], rb[lo], rb[lo + 2]);
            }
        }
    }

    const int mrow = m0 + warp_m + (lane >> 2);
    const int ncol = n0 + warp_n + (lane & 3) * 2;
    #pragma unroll
    for (int mi = 0; mi < 2; mi++) {
        #pragma unroll
        for (int nj = 0; nj < 8; nj++) {
            int r = mrow + mi * 16;
            int c = ncol + nj * 8;
            float bv0 = bias[c], bv1 = bias[c + 1];
            float v00 = acc[mi][nj][0] + bv0, v01 = acc[mi][nj][1] + bv1;
            float v10 = acc[mi][nj][2] + bv0, v11 = acc[mi][nj][3] + bv1;
            if (Cl) {
                uint32_t h0, l0, h1, l1;
                pack_hl(v00, v01, h0, l0);
                pack_hl(v10, v11, h1, l1);
                *(uint32_t*)(Ch + (size_t)r * N + c) = h0;
                *(uint32_t*)(Cl + (size_t)r * N + c) = l0;
                *(uint32_t*)(Ch + (size_t)(r + 8) * N + c) = h1;
                *(uint32_t*)(Cl + (size_t)(r + 8) * N + c) = l1;
            } else {
                *(float2*)(C + (size_t)r * N + c) = make_float2(v00, v01);
                *(float2*)(C + (size_t)(r + 8) * N + c) = make_float2(v10, v11);
            }
        }
    }
}

// ---------------------------------------------------------------------------
// HMMA flash attention (causal), bf16x3 S and PV, fp32 softmax/accum.
// UNCHANGED math from R14 except epilogue emits fp16 hi/lo for proj GEMM.
// ---------------------------------------------------------------------------
#define AQH 0
#define AQL (128 * LDS_PAD)
#define AKH (2 * 128 * LDS_PAD)
#define AKL (AKH + 64 * LDS_PAD)
#define AVH (AKL + 64 * LDS_PAD)
#define AVL (AVH + 64 * LDS_PAD)
#define ATTN_SMEM ((AVL + 64 * LDS_PAD) * 2)

__global__ __launch_bounds__(256, 2) void mma_attn_kernel(
    const __nv_bfloat16* __restrict__ qkvh, const __nv_bfloat16* __restrict__ qkvl,
    __half* __restrict__ yh, __half* __restrict__ yl)
{
    extern __shared__ __nv_bfloat16 sm[];
    const int tid = threadIdx.x;
    const int wid = tid >> 5;
    const int lane = tid & 31;
    const int qt = gridDim.x - 1 - blockIdx.x;     // heavy tiles first
    const int bh = blockIdx.y;
    const int b = bh / NH;
    const int h = bh % NH;
    const size_t base = (size_t)b * T_SEQ * QKV_N;
    const int qoff = h * DH;
    const int koff = DMODEL + h * DH;
    const int voff = 2 * DMODEL + h * DH;
    const uint32_t sbase = smem_u32(sm);

    const int a_row = (lane & 15);
    const int a_coff = (lane >> 4) * 8;
    const int b_row = (lane & 7) + ((lane >> 3) & 1) * 8;
    const int b_coff = ((lane >> 4) & 1) * 8;
    const int v_krow = ((lane >> 3) & 1) * 8 + (lane & 7);
    const int v_ncol = ((lane >> 4) & 1) * 8;

    // ---- load Q tile (hi/lo) via cp.async ----
    #pragma unroll
    for (int it = 0; it < 4; it++) {
        int idx = tid + it * 256;        // 0..1023
        int row = idx >> 3, g = idx & 7;
        size_t goff = base + (size_t)(qt * 128 + row) * QKV_N + qoff + g * 8;
        uint32_t so = (uint32_t)(row * LDS_PAD + g * 8) * 2;
        cp16(sbase + (AQH * 2) + so, qkvh + goff);
        cp16(sbase + (AQL * 2) + so, qkvl + goff);
    }
    CP_COMMIT();

    float oacc[8][4];
    #pragma unroll
    for (int nj = 0; nj < 8; nj++)
        #pragma unroll
        for (int q = 0; q < 4; q++) oacc[nj][q] = 0.0f;
    float m_a = -1e30f, m_b = -1e30f, l_a = 0.0f, l_b = 0.0f;

    const int gr_a = qt * 128 + wid * 16 + (lane >> 2);
    const int gr_b = gr_a + 8;
    const int nkt = 2 * qt + 2;

    #pragma unroll 1
    for (int kt = 0; kt < nkt; kt++) {
        __syncthreads();
        #pragma unroll
        for (int it = 0; it < 8; it++) {
            int idx = tid + it * 256;     // 0..2047
            int tile = idx >> 9;          // 0:Kh 1:Kl 2:Vh 3:Vl
            int r = (idx >> 3) & 63;
            int g = idx & 7;
            const __nv_bfloat16* src = (tile & 1) ? qkvl : qkvh;
            int off = (tile < 2) ? koff : voff;
            int dsto = (tile == 0) ? AKH : (tile == 1) ? AKL : (tile == 2) ? AVH : AVL;
            cp16(sbase + (uint32_t)(dsto + r * LDS_PAD + g * 8) * 2,
                 src + base + (size_t)(kt * 64 + r) * QKV_N + off + g * 8);
        }
        CP_COMMIT();
        CP_WAIT0();
        __syncthreads();

        // ---- S = Qh*Kh + Ql*Kh + Qh*Kl ----
        float sacc[8][4];
        #pragma unroll
        for (int nj = 0; nj < 8; nj++)
            #pragma unroll
            for (int q = 0; q < 4; q++) sacc[nj][q] = 0.0f;

        #pragma unroll
        for (int ks = 0; ks < 4; ks++) {
            const int k0 = ks * 16;
            uint32_t qh[4], ql[4];
            ldsm_x4(qh[0], qh[1], qh[2], qh[3],
                    sbase + (AQH + (wid * 16 + a_row) * LDS_PAD + k0 + a_coff) * 2);
            ldsm_x4(ql[0], ql[1], ql[2], ql[3],
                    sbase + (AQL + (wid * 16 + a_row) * LDS_PAD + k0 + a_coff) * 2);
            #pragma unroll
            for (int nb = 0; nb < 4; nb++) {
                uint32_t br = (nb * 16 + b_row) * LDS_PAD + k0 + b_coff;
                uint32_t rb[4];
                ldsm_x4(rb[0], rb[1], rb[2], rb[3], sbase + (AKH + br) * 2);
                #pragma unroll
                for (int lo = 0; lo < 2; lo++)
                    mma_bf16(sacc[2 * nb + lo], qh, rb[lo], rb[lo + 2]);
                #pragma unroll
                for (int lo = 0; lo < 2; lo++)
                    mma_bf16(sacc[2 * nb + lo], ql, rb[lo], rb[lo + 2]);
                ldsm_x4(rb[0], rb[1], rb[2], rb[3], sbase + (AKL + br) * 2);
                #pragma unroll
                for (int lo = 0; lo < 2; lo++)
                    mma_bf16(sacc[2 * nb + lo], qh, rb[lo], rb[lo + 2]);
            }
        }

        // ---- scale + causal mask ----
        const bool diag = (kt >= 2 * qt);
        #pragma unroll
        for (int nj = 0; nj < 8; nj++) {
            #pragma unroll
            for (int q = 0; q < 4; q++) sacc[nj][q] *= 0.125f;
            if (diag) {
                int gc = kt * 64 + nj * 8 + (lane & 3) * 2;
                if (gc > gr_a)     sacc[nj][0] = -1e30f;
                if (gc + 1 > gr_a) sacc[nj][1] = -1e30f;
                if (gc > gr_b)     sacc[nj][2] = -1e30f;
                if (gc + 1 > gr_b) sacc[nj][3] = -1e30f;
            }
        }

        // ---- online softmax ----
        float mx_a = -1e30f, mx_b = -1e30f;
        #pragma unroll
        for (int nj = 0; nj < 8; nj++) {
            mx_a = fmaxf(mx_a, fmaxf(sacc[nj][0], sacc[nj][1]));
            mx_b = fmaxf(mx_b, fmaxf(sacc[nj][2], sacc[nj][3]));
        }
        mx_a = fmaxf(mx_a, __shfl_xor_sync(0xffffffffu, mx_a, 1));
        mx_a = fmaxf(mx_a, __shfl_xor_sync(0xffffffffu, mx_a, 2));
        mx_b = fmaxf(mx_b, __shfl_xor_sync(0xffffffffu, mx_b, 1));
        mx_b = fmaxf(mx_b, __shfl_xor_sync(0xffffffffu, mx_b, 2));
        float mn_a = fmaxf(m_a, mx_a), mn_b = fmaxf(m_b, mx_b);
        float corr_a = __expf(m_a - mn_a), corr_b = __expf(m_b - mn_b);
        float sum_a = 0.0f, sum_b = 0.0f;
        #pragma unroll
        for (int nj = 0; nj < 8; nj++) {
            sacc[nj][0] = __expf(sacc[nj][0] - mn_a);
            sacc[nj][1] = __expf(sacc[nj][1] - mn_a);
            sacc[nj][2] = __expf(sacc[nj][2] - mn_b);
            sacc[nj][3] = __expf(sacc[nj][3] - mn_b);
            sum_a += sacc[nj][0] + sacc[nj][1];
            sum_b += sacc[nj][2] + sacc[nj][3];
        }
        sum_a += __shfl_xor_sync(0xffffffffu, sum_a, 1);
        sum_a += __shfl_xor_sync(0xffffffffu, sum_a, 2);
        sum_b += __shfl_xor_sync(0xffffffffu, sum_b, 1);
        sum_b += __shfl_xor_sync(0xffffffffu, sum_b, 2);
        l_a = l_a * corr_a + sum_a;
        l_b = l_b * corr_b + sum_b;
        m_a = mn_a; m_b = mn_b;
        #pragma unroll
        for (int nj = 0; nj < 8; nj++) {
            oacc[nj][0] *= corr_a; oacc[nj][1] *= corr_a;
            oacc[nj][2] *= corr_b; oacc[nj][3] *= corr_b;
        }

        // ---- O += (Ph+Pl) * (Vh+Vl) : PhVh + PlVh + PhVl ----
        #pragma unroll
        for (int kb = 0; kb < 4; kb++) {
            uint32_t pa_h[4], pa_l[4];
            pack_hl(sacc[2 * kb][0], sacc[2 * kb][1], pa_h[0], pa_l[0]);
            pack_hl(sacc[2 * kb][2], sacc[2 * kb][3], pa_h[1], pa_l[1]);
            pack_hl(sacc[2 * kb + 1][0], sacc[2 * kb + 1][1], pa_h[2], pa_l[2]);
            pack_hl(sacc[2 * kb + 1][2], sacc[2 * kb + 1][3], pa_h[3], pa_l[3]);
            #pragma unroll
            for (int nout = 0; nout < 4; nout++) {
                uint32_t rv[4];
                ldsm_x4_t(rv[0], rv[1], rv[2], rv[3],
                          sbase + (AVH + (kb * 16 + v_krow) * LDS_PAD + nout * 16 + v_ncol) * 2);
                mma_bf16(oacc[2 * nout], pa_h, rv[0], rv[1]);
                mma_bf16(oacc[2 * nout + 1], pa_h, rv[2], rv[3]);
                mma_bf16(oacc[2 * nout], pa_l, rv[0], rv[1]);
                mma_bf16(oacc[2 * nout + 1], pa_l, rv[2], rv[3]);
                ldsm_x4_t(rv[0], rv[1], rv[2], rv[3],
                          sbase + (AVL + (kb * 16 + v_krow) * LDS_PAD + nout * 16 + v_ncol) * 2);
                mma_bf16(oacc[2 * nout], pa_h, rv[0], rv[1]);
                mma_bf16(oacc[2 * nout + 1], pa_h, rv[2], rv[3]);
            }
        }
    }

    // ---- epilogue: y = O / l, split fp16 hi/lo ----
    const float inv_a = 1.0f / l_a;
    const float inv_b = 1.0f / l_b;
    #pragma unroll
    for (int nj = 0; nj < 8; nj++) {
        int col = h * DH + nj * 8 + (lane & 3) * 2;
        size_t ra = (size_t)(b * T_SEQ + gr_a) * DMODEL + col;
        size_t rb2 = (size_t)(b * T_SEQ + gr_b) * DMODEL + col;
        uint32_t h0, l0, h1, l1;
        pack_hl_f16(oacc[nj][0] * inv_a, oacc[nj][1] * inv_a, h0, l0);
        pack_hl_f16(oacc[nj][2] * inv_b, oacc[nj][3] * inv_b, h1, l1);
        *(uint32_t*)(yh + ra) = h0;
        *(uint32_t*)(yl + ra) = l0;
        *(uint32_t*)(yh + rb2) = h1;
        *(uint32_t*)(yl + rb2) = l1;
    }
}

// ---------------------------------------------------------------------------
// fp32 -> (hi, lo) fp16 split
// ---------------------------------------------------------------------------
__global__ __launch_bounds__(256) void split_kernel_f16(
    const float* __restrict__ in, __half* __restrict__ hi,
    __half* __restrict__ lo, int n4)
{
    int i = blockIdx.x * blockDim.x + threadIdx.x;
    if (i >= n4) return;
    float4 v = *(const float4*)(in + (size_t)i * 4);
    __half h[4], l[4];
    float f[4] = {v.x, v.y, v.z, v.w};
    #pragma unroll
    for (int k = 0; k < 4; ++k) {
        h[k] = __float2half_rn(f[k]);
        l[k] = __float2half_rn(f[k] - __half2float(h[k]));
    }
    *(uint2*)(hi + (size_t)i * 4) = *(uint2*)h;
    *(uint2*)(lo + (size_t)i * 4) = *(uint2*)l;
}

// ---------------------------------------------------------------------------
// W [K,N] fp32 -> fl16(W^T) [N,K]   (hi only — 2-term scheme)
// ---------------------------------------------------------------------------
__global__ __launch_bounds__(256) void transpose_f16_kernel(
    const float* __restrict__ W, __half* __restrict__ hiT, int K, int N)
{
    __shared__ float tile[32][33];
    const int tx = threadIdx.x;
    const int ty = threadIdx.y;
    const int k0 = blockIdx.y * 32;
    const int n0 = blockIdx.x * 32;
    #pragma unroll
    for (int r = 0; r < 32; r += 8)
        tile[ty + r][tx] = W[(size_t)(k0 + ty + r) * N + n0 + tx];
    __syncthreads();
    #pragma unroll
    for (int r = 0; r < 32; r += 8)
        hiT[(size_t)(n0 + ty + r) * K + k0 + tx] = __float2half_rn(tile[tx][ty + r]);
}

// ---------------------------------------------------------------------------
extern "C" void kernel_launch(void* const* d_in, const int* in_sizes, int n_in,
                              void* d_out, int out_size)
{
    const float* x      = (const float*)d_in[0];
    const float* w_attn = (const float*)d_in[1];
    const float* b_attn = (const float*)d_in[2];
    const float* w_proj = (const float*)d_in[3];
    const float* b_proj = (const float*)d_in[4];
    float* out = (float*)d_out;

    __nv_bfloat16 *qkvh, *qkvl;
    __half *xh, *xl, *yh, *yl, *wah, *wph;
    cudaGetSymbolAddress((void**)&qkvh, g_qkvh);
    cudaGetSymbolAddress((void**)&qkvl, g_qkvl);
    cudaGetSymbolAddress((void**)&xh, g_xh);
    cudaGetSymbolAddress((void**)&xl, g_xl);
    cudaGetSymbolAddress((void**)&yh, g_yh);
    cudaGetSymbolAddress((void**)&yl, g_yl);
    cudaGetSymbolAddress((void**)&wah, g_wah);
    cudaGetSymbolAddress((void**)&wph, g_wph);

    static bool attr_set = false;
    if (!attr_set) {
        cudaFuncSetAttribute(mma_attn_kernel,
                             cudaFuncAttributeMaxDynamicSharedMemorySize, ATTN_SMEM);
        cudaFuncSetAttribute(mma_gemm_kernel,
                             cudaFuncAttributeMaxDynamicSharedMemorySize, GEMM_SMEM);
        attr_set = true;
    }

    // 0) conversions
    {
        int n4 = (M_ROWS * DMODEL) / 4;
        split_kernel_f16<<<(n4 + 255) / 256, 256>>>(x, xh, xl, n4);
        dim3 blk(32, 8);
        transpose_f16_kernel<<<dim3(QKV_N / 32, DMODEL / 32), blk>>>(w_attn, wah, DMODEL, QKV_N);
        transpose_f16_kernel<<<dim3(DMODEL / 32, DMODEL / 32), blk>>>(w_proj, wph, DMODEL, DMODEL);
    }
    // 1) QKV GEMM (fp16 2-term) -> bf16 hi/lo qkv
    {
        dim3 grid(QKV_N / 128, M_ROWS / 128);
        mma_gemm_kernel<<<grid, 256, GEMM_SMEM>>>(xh, xl, wah, b_attn,
                                                  nullptr, qkvh, qkvl, QKV_N);
    }
    // 2) causal flash attention (bf16x3) -> fp16 hi/lo y
    {
        dim3 grid(T_SEQ / 128, BATCH * NH);   // (16, 48)
        mma_attn_kernel<<<grid, 256, ATTN_SMEM>>>(qkvh, qkvl, yh, yl);
    }
    // 3) out projection (fp16 2-term) -> fp32 out
    {
        dim3 grid(DMODEL / 128, M_ROWS / 128);
        mma_gemm_kernel<<<grid, 256, GEMM_SMEM>>>(yh, yl, wph, b_proj,
                                                  out, nullptr, nullptr, DMODEL);
    }
}

// round 16
// speedup vs baseline: 2.1308x; 1.1610x over previous
#include <cuda_runtime.h>
#include <cuda_bf16.h>
#include <cuda_fp16.h>
#include <cstdint>
#include <math.h>

#define BATCH 4
#define T_SEQ 2048
#define NH 12
#define DMODEL 768
#define DH 64
#define M_ROWS (BATCH * T_SEQ)          // 8192
#define QKV_N (3 * DMODEL)              // 2304
#define GK DMODEL                       // GEMM K = 768
#define LDS_PAD 72                      // smem row stride in 16-bit elems (144 B)

// ------------------------- scratch (static, allocation-free) ---------------
__device__ __half g_qkvh[(size_t)M_ROWS * QKV_N];
__device__ __half g_qkvl[(size_t)M_ROWS * QKV_N];
__device__ __half g_xh[(size_t)M_ROWS * DMODEL];
__device__ __half g_xl[(size_t)M_ROWS * DMODEL];
__device__ __half g_yh[(size_t)M_ROWS * DMODEL];
__device__ __half g_yl[(size_t)M_ROWS * DMODEL];
__device__ __half g_wah[(size_t)QKV_N * DMODEL];   // fl16(w_attn^T) [2304,768]
__device__ __half g_wph[(size_t)DMODEL * DMODEL];  // fl16(w_proj^T) [768,768]

// ------------------------- helpers -----------------------------------------
__device__ __forceinline__ uint32_t smem_u32(const void* p) {
    uint32_t a;
    asm("{ .reg .u64 t; cvta.to.shared.u64 t, %1; cvt.u32.u64 %0, t; }" : "=r"(a) : "l"(p));
    return a;
}
__device__ __forceinline__ void cp16(uint32_t dst, const void* src) {
    asm volatile("cp.async.cg.shared.global [%0], [%1], 16;" :: "r"(dst), "l"(src));
}
#define CP_COMMIT() asm volatile("cp.async.commit_group;" ::: "memory")
#define CP_WAIT0()  asm volatile("cp.async.wait_group 0;" ::: "memory")

__device__ __forceinline__ void ldsm_x4(uint32_t& r0, uint32_t& r1,
                                        uint32_t& r2, uint32_t& r3, uint32_t addr) {
    asm volatile("ldmatrix.sync.aligned.m8n8.x4.shared.b16 {%0,%1,%2,%3}, [%4];"
                 : "=r"(r0), "=r"(r1), "=r"(r2), "=r"(r3) : "r"(addr));
}
__device__ __forceinline__ void ldsm_x4_t(uint32_t& r0, uint32_t& r1,
                                          uint32_t& r2, uint32_t& r3, uint32_t addr) {
    asm volatile("ldmatrix.sync.aligned.m8n8.x4.trans.shared.b16 {%0,%1,%2,%3}, [%4];"
                 : "=r"(r0), "=r"(r1), "=r"(r2), "=r"(r3) : "r"(addr));
}
__device__ __forceinline__ void mma_f16(float* c, const uint32_t* a,
                                        uint32_t b0, uint32_t b1) {
    asm volatile(
        "mma.sync.aligned.m16n8k16.row.col.f32.f16.f16.f32 "
        "{%0,%1,%2,%3}, {%4,%5,%6,%7}, {%8,%9}, {%0,%1,%2,%3};"
        : "+f"(c[0]), "+f"(c[1]), "+f"(c[2]), "+f"(c[3])
        : "r"(a[0]), "r"(a[1]), "r"(a[2]), "r"(a[3]), "r"(b0), "r"(b1));
}
__device__ __forceinline__ void pack_hl_f16(float f0, float f1, uint32_t& h, uint32_t& l) {
    __half h0 = __float2half_rn(f0), h1 = __float2half_rn(f1);
    __half2 hh = __halves2half2(h0, h1);
    h = *(uint32_t*)&hh;
    __half2 ll = __halves2half2(__float2half_rn(f0 - __half2float(h0)),
                                __float2half_rn(f1 - __half2float(h1)));
    l = *(uint32_t*)&ll;
}

// ---------------------------------------------------------------------------
// HMMA GEMM, fp16 2-term: C = (Ah + Al) * Bh + bias  ==  A * fl16(B) + bias
// Per K-chunk (64): load Ah|Al|Bh tiles once via cp.async. 32 MMAs per ks.
// 256 threads = 8 warps (4M x 2N), warp tile 32x64, 2 CTAs/SM.
// Output: fp32 C (Cl==nullptr) or fp16 hi/lo split (Ch,Cl).
// ---------------------------------------------------------------------------
#define GOAH 0
#define GOAL (128 * LDS_PAD)
#define GOBH (2 * 128 * LDS_PAD)
#define GEMM_SMEM (3 * 128 * LDS_PAD * 2)    // 55296 bytes

__global__ __launch_bounds__(256, 2) void mma_gemm_kernel(
    const __half* __restrict__ Ah, const __half* __restrict__ Al,
    const __half* __restrict__ Bh,
    const float* __restrict__ bias, float* __restrict__ C,
    __half* __restrict__ Ch, __half* __restrict__ Cl, int N)
{
    extern __shared__ __half gsm[];
    const int tid  = threadIdx.x;
    const int wid  = tid >> 5;
    const int lane = tid & 31;
    const int m0 = blockIdx.y * 128;
    const int n0 = blockIdx.x * 128;
    const int warp_m = (wid >> 1) * 32;
    const int warp_n = (wid & 1) * 64;
    const uint32_t sbase = smem_u32(gsm);

    const int a_row = (lane & 15);
    const int a_coff = (lane >> 4) * 8;
    const int b_row = (lane & 7) + ((lane >> 3) & 1) * 8;
    const int b_coff = ((lane >> 4) & 1) * 8;

    float acc[2][8][4];
    #pragma unroll
    for (int mi = 0; mi < 2; mi++)
        #pragma unroll
        for (int nj = 0; nj < 8; nj++)
            #pragma unroll
            for (int q = 0; q < 4; q++) acc[mi][nj][q] = 0.0f;

    #pragma unroll 1
    for (int kc = 0; kc < GK; kc += 64) {
        __syncthreads();
        // load 3 tiles (128 rows x 64 halves each): 3072 granules, 12/thread
        #pragma unroll
        for (int it = 0; it < 12; it++) {
            int idx = tid + it * 256;          // 0..3071
            int tile = idx >> 10;              // 0:Ah 1:Al 2:Bh
            int rem = idx & 1023;
            int row = rem >> 3;                // 0..127
            int g   = rem & 7;                 // 16B granule
            const __half* sp = (tile == 0) ? Ah : (tile == 1) ? Al : Bh;
            int rbase = (tile < 2) ? m0 : n0;
            cp16(sbase + (uint32_t)(tile * 128 * LDS_PAD + row * LDS_PAD + g * 8) * 2,
                 sp + (size_t)(rbase + row) * GK + kc + g * 8);
        }
        CP_COMMIT();
        CP_WAIT0();
        __syncthreads();

        #pragma unroll
        for (int ks = 0; ks < 4; ks++) {
            const int k0 = ks * 16;
            uint32_t rah[2][4], ral[2][4];
            #pragma unroll
            for (int mi = 0; mi < 2; mi++) {
                uint32_t ar = (warp_m + mi * 16 + a_row) * LDS_PAD + k0 + a_coff;
                ldsm_x4(rah[mi][0], rah[mi][1], rah[mi][2], rah[mi][3],
                        sbase + (GOAH + ar) * 2);
                ldsm_x4(ral[mi][0], ral[mi][1], ral[mi][2], ral[mi][3],
                        sbase + (GOAL + ar) * 2);
            }
            #pragma unroll
            for (int nb = 0; nb < 4; nb++) {
                uint32_t br = (warp_n + nb * 16 + b_row) * LDS_PAD + k0 + b_coff;
                uint32_t rb[4];
                ldsm_x4(rb[0], rb[1], rb[2], rb[3], sbase + (GOBH + br) * 2);
                // 4 independent hh MMAs, then 4 lh (per-acc order preserved)
                #pragma unroll
                for (int lo = 0; lo < 2; lo++)
                    #pragma unroll
                    for (int mi = 0; mi < 2; mi++)
                        mma_f16(acc[mi][2 * nb + lo], rah[mi], rb[lo], rb[lo + 2]);
                #pragma unroll
                for (int lo = 0; lo < 2; lo++)
                    #pragma unroll
                    for (int mi = 0; mi < 2; mi++)
                        mma_f16(acc[mi][2 * nb + lo], ral[mi], rb[lo], rb[lo + 2]);
            }
        }
    }

    const int mrow = m0 + warp_m + (lane >> 2);
    const int ncol = n0 + warp_n + (lane & 3) * 2;
    #pragma unroll
    for (int mi = 0; mi < 2; mi++) {
        #pragma unroll
        for (int nj = 0; nj < 8; nj++) {
            int r = mrow + mi * 16;
            int c = ncol + nj * 8;
            float bv0 = bias[c], bv1 = bias[c + 1];
            float v00 = acc[mi][nj][0] + bv0, v01 = acc[mi][nj][1] + bv1;
            float v10 = acc[mi][nj][2] + bv0, v11 = acc[mi][nj][3] + bv1;
            if (Cl) {
                uint32_t h0, l0, h1, l1;
                pack_hl_f16(v00, v01, h0, l0);
                pack_hl_f16(v10, v11, h1, l1);
                *(uint32_t*)(Ch + (size_t)r * N + c) = h0;
                *(uint32_t*)(Cl + (size_t)r * N + c) = l0;
                *(uint32_t*)(Ch + (size_t)(r + 8) * N + c) = h1;
                *(uint32_t*)(Cl + (size_t)(r + 8) * N + c) = l1;
            } else {
                *(float2*)(C + (size_t)r * N + c) = make_float2(v00, v01);
                *(float2*)(C + (size_t)(r + 8) * N + c) = make_float2(v10, v11);
            }
        }
    }
}

// ---------------------------------------------------------------------------
// HMMA flash attention (causal), fp16 2-term S and PV, fp32 softmax/accum.
//   S  = (Qh+Ql) * fl16(K)   — Q hi/lo, K hi only
//   O += (Ph+Pl) * fl16(V)   — P split exactly in fp16, V hi only
// Grid (T/128, B*NH), 256 threads = 8 warps x 16 Q-rows. K/V tiles 64 rows.
// ---------------------------------------------------------------------------
#define AQH 0
#define AQL (128 * LDS_PAD)
#define AKH (2 * 128 * LDS_PAD)
#define AVH (AKH + 64 * LDS_PAD)
#define ATTN_SMEM ((AVH + 64 * LDS_PAD) * 2)   // 55296 bytes

__global__ __launch_bounds__(256, 2) void mma_attn_kernel(
    const __half* __restrict__ qkvh, const __half* __restrict__ qkvl,
    __half* __restrict__ yh, __half* __restrict__ yl)
{
    extern __shared__ __half sm[];
    const int tid = threadIdx.x;
    const int wid = tid >> 5;
    const int lane = tid & 31;
    const int qt = gridDim.x - 1 - blockIdx.x;     // heavy tiles first
    const int bh = blockIdx.y;
    const int b = bh / NH;
    const int h = bh % NH;
    const size_t base = (size_t)b * T_SEQ * QKV_N;
    const int qoff = h * DH;
    const int koff = DMODEL + h * DH;
    const int voff = 2 * DMODEL + h * DH;
    const uint32_t sbase = smem_u32(sm);

    const int a_row = (lane & 15);
    const int a_coff = (lane >> 4) * 8;
    const int b_row = (lane & 7) + ((lane >> 3) & 1) * 8;
    const int b_coff = ((lane >> 4) & 1) * 8;
    const int v_krow = ((lane >> 3) & 1) * 8 + (lane & 7);
    const int v_ncol = ((lane >> 4) & 1) * 8;

    // ---- load Q tile (hi/lo) via cp.async ----
    #pragma unroll
    for (int it = 0; it < 4; it++) {
        int idx = tid + it * 256;        // 0..1023
        int row = idx >> 3, g = idx & 7;
        size_t goff = base + (size_t)(qt * 128 + row) * QKV_N + qoff + g * 8;
        uint32_t so = (uint32_t)(row * LDS_PAD + g * 8) * 2;
        cp16(sbase + (AQH * 2) + so, qkvh + goff);
        cp16(sbase + (AQL * 2) + so, qkvl + goff);
    }
    CP_COMMIT();

    float oacc[8][4];
    #pragma unroll
    for (int nj = 0; nj < 8; nj++)
        #pragma unroll
        for (int q = 0; q < 4; q++) oacc[nj][q] = 0.0f;
    float m_a = -1e30f, m_b = -1e30f, l_a = 0.0f, l_b = 0.0f;

    const int gr_a = qt * 128 + wid * 16 + (lane >> 2);
    const int gr_b = gr_a + 8;
    const int nkt = 2 * qt + 2;

    #pragma unroll 1
    for (int kt = 0; kt < nkt; kt++) {
        __syncthreads();
        // ---- load Kh|Vh tiles via cp.async: 2 x 64 rows x 8 granules ----
        #pragma unroll
        for (int it = 0; it < 4; it++) {
            int idx = tid + it * 256;     // 0..1023
            int tile = idx >> 9;          // 0:Kh 1:Vh
            int r = (idx >> 3) & 63;
            int g = idx & 7;
            int off = (tile == 0) ? koff : voff;
            int dsto = (tile == 0) ? AKH : AVH;
            cp16(sbase + (uint32_t)(dsto + r * LDS_PAD + g * 8) * 2,
                 qkvh + base + (size_t)(kt * 64 + r) * QKV_N + off + g * 8);
        }
        CP_COMMIT();
        CP_WAIT0();
        __syncthreads();

        // ---- S = (Qh+Ql) * Kh ----
        float sacc[8][4];
        #pragma unroll
        for (int nj = 0; nj < 8; nj++)
            #pragma unroll
            for (int q = 0; q < 4; q++) sacc[nj][q] = 0.0f;

        #pragma unroll
        for (int ks = 0; ks < 4; ks++) {
            const int k0 = ks * 16;
            uint32_t qh[4], ql[4];
            ldsm_x4(qh[0], qh[1], qh[2], qh[3],
                    sbase + (AQH + (wid * 16 + a_row) * LDS_PAD + k0 + a_coff) * 2);
            ldsm_x4(ql[0], ql[1], ql[2], ql[3],
                    sbase + (AQL + (wid * 16 + a_row) * LDS_PAD + k0 + a_coff) * 2);
            #pragma unroll
            for (int nb = 0; nb < 4; nb++) {
                uint32_t br = (nb * 16 + b_row) * LDS_PAD + k0 + b_coff;
                uint32_t rb[4];
                ldsm_x4(rb[0], rb[1], rb[2], rb[3], sbase + (AKH + br) * 2);
                // 2 independent hh, then 2 lh (per-acc order preserved)
                #pragma unroll
                for (int lo = 0; lo < 2; lo++)
                    mma_f16(sacc[2 * nb + lo], qh, rb[lo], rb[lo + 2]);
                #pragma unroll
                for (int lo = 0; lo < 2; lo++)
                    mma_f16(sacc[2 * nb + lo], ql, rb[lo], rb[lo + 2]);
            }
        }

        // ---- scale + causal mask ----
        const bool diag = (kt >= 2 * qt);
        #pragma unroll
        for (int nj = 0; nj < 8; nj++) {
            #pragma unroll
            for (int q = 0; q < 4; q++) sacc[nj][q] *= 0.125f;
            if (diag) {
                int gc = kt * 64 + nj * 8 + (lane & 3) * 2;
                if (gc > gr_a)     sacc[nj][0] = -1e30f;
                if (gc + 1 > gr_a) sacc[nj][1] = -1e30f;
                if (gc > gr_b)     sacc[nj][2] = -1e30f;
                if (gc + 1 > gr_b) sacc[nj][3] = -1e30f;
            }
        }

        // ---- online softmax ----
        float mx_a = -1e30f, mx_b = -1e30f;
        #pragma unroll
        for (int nj = 0; nj < 8; nj++) {
            mx_a = fmaxf(mx_a, fmaxf(sacc[nj][0], sacc[nj][1]));
            mx_b = fmaxf(mx_b, fmaxf(sacc[nj][2], sacc[nj][3]));
        }
        mx_a = fmaxf(mx_a, __shfl_xor_sync(0xffffffffu, mx_a, 1));
        mx_a = fmaxf(mx_a, __shfl_xor_sync(0xffffffffu, mx_a, 2));
        mx_b = fmaxf(mx_b, __shfl_xor_sync(0xffffffffu, mx_b, 1));
        mx_b = fmaxf(mx_b, __shfl_xor_sync(0xffffffffu, mx_b, 2));
        float mn_a = fmaxf(m_a, mx_a), mn_b = fmaxf(m_b, mx_b);
        float corr_a = __expf(m_a - mn_a), corr_b = __expf(m_b - mn_b);
        float sum_a = 0.0f, sum_b = 0.0f;
        #pragma unroll
        for (int nj = 0; nj < 8; nj++) {
            sacc[nj][0] = __expf(sacc[nj][0] - mn_a);
            sacc[nj][1] = __expf(sacc[nj][1] - mn_a);
            sacc[nj][2] = __expf(sacc[nj][2] - mn_b);
            sacc[nj][3] = __expf(sacc[nj][3] - mn_b);
            sum_a += sacc[nj][0] + sacc[nj][1];
            sum_b += sacc[nj][2] + sacc[nj][3];
        }
        sum_a += __shfl_xor_sync(0xffffffffu, sum_a, 1);
        sum_a += __shfl_xor_sync(0xffffffffu, sum_a, 2);
        sum_b += __shfl_xor_sync(0xffffffffu, sum_b, 1);
        sum_b += __shfl_xor_sync(0xffffffffu, sum_b, 2);
        l_a = l_a * corr_a + sum_a;
        l_b = l_b * corr_b + sum_b;
        m_a = mn_a; m_b = mn_b;
        #pragma unroll
        for (int nj = 0; nj < 8; nj++) {
            oacc[nj][0] *= corr_a; oacc[nj][1] *= corr_a;
            oacc[nj][2] *= corr_b; oacc[nj][3] *= corr_b;
        }

        // ---- O += (Ph+Pl) * Vh ----
        #pragma unroll
        for (int kb = 0; kb < 4; kb++) {
            uint32_t pa_h[4], pa_l[4];
            pack_hl_f16(sacc[2 * kb][0], sacc[2 * kb][1], pa_h[0], pa_l[0]);
            pack_hl_f16(sacc[2 * kb][2], sacc[2 * kb][3], pa_h[1], pa_l[1]);
            pack_hl_f16(sacc[2 * kb + 1][0], sacc[2 * kb + 1][1], pa_h[2], pa_l[2]);
            pack_hl_f16(sacc[2 * kb + 1][2], sacc[2 * kb + 1][3], pa_h[3], pa_l[3]);
            #pragma unroll
            for (int nout = 0; nout < 4; nout++) {
                uint32_t rv[4];
                ldsm_x4_t(rv[0], rv[1], rv[2], rv[3],
                          sbase + (AVH + (kb * 16 + v_krow) * LDS_PAD + nout * 16 + v_ncol) * 2);
                // 2 independent pa_h, then 2 pa_l (per-acc order preserved)
                mma_f16(oacc[2 * nout], pa_h, rv[0], rv[1]);
                mma_f16(oacc[2 * nout + 1], pa_h, rv[2], rv[3]);
                mma_f16(oacc[2 * nout], pa_l, rv[0], rv[1]);
                mma_f16(oacc[2 * nout + 1], pa_l, rv[2], rv[3]);
            }
        }
    }

    // ---- epilogue: y = O / l, split fp16 hi/lo ----
    const float inv_a = 1.0f / l_a;
    const float inv_b = 1.0f / l_b;
    #pragma unroll
    for (int nj = 0; nj < 8; nj++) {
        int col = h * DH + nj * 8 + (lane & 3) * 2;
        size_t ra = (size_t)(b * T_SEQ + gr_a) * DMODEL + col;
        size_t rb2 = (size_t)(b * T_SEQ + gr_b) * DMODEL + col;
        uint32_t h0, l0, h1, l1;
        pack_hl_f16(oacc[nj][0] * inv_a, oacc[nj][1] * inv_a, h0, l0);
        pack_hl_f16(oacc[nj][2] * inv_b, oacc[nj][3] * inv_b, h1, l1);
        *(uint32_t*)(yh + ra) = h0;
        *(uint32_t*)(yl + ra) = l0;
        *(uint32_t*)(yh + rb2) = h1;
        *(uint32_t*)(yl + rb2) = l1;
    }
}

// ---------------------------------------------------------------------------
// fp32 -> (hi, lo) fp16 split
// ---------------------------------------------------------------------------
__global__ __launch_bounds__(256) void split_kernel_f16(
    const float* __restrict__ in, __half* __restrict__ hi,
    __half* __restrict__ lo, int n4)
{
    int i = blockIdx.x * blockDim.x + threadIdx.x;
    if (i >= n4) return;
    float4 v = *(const float4*)(in + (size_t)i * 4);
    __half h[4], l[4];
    float f[4] = {v.x, v.y, v.z, v.w};
    #pragma unroll
    for (int k = 0; k < 4; ++k) {
        h[k] = __float2half_rn(f[k]);
        l[k] = __float2half_rn(f[k] - __half2float(h[k]));
    }
    *(uint2*)(hi + (size_t)i * 4) = *(uint2*)h;
    *(uint2*)(lo + (size_t)i * 4) = *(uint2*)l;
}

// ---------------------------------------------------------------------------
// W [K,N] fp32 -> fl16(W^T) [N,K]   (hi only — 2-term scheme)
// ---------------------------------------------------------------------------
__global__ __launch_bounds__(256) void transpose_f16_kernel(
    const float* __restrict__ W, __half* __restrict__ hiT, int K, int N)
{
    __shared__ float tile[32][33];
    const int tx = threadIdx.x;
    const int ty = threadIdx.y;
    const int k0 = blockIdx.y * 32;
    const int n0 = blockIdx.x * 32;
    #pragma unroll
    for (int r = 0; r < 32; r += 8)
        tile[ty + r][tx] = W[(size_t)(k0 + ty + r) * N + n0 + tx];
    __syncthreads();
    #pragma unroll
    for (int r = 0; r < 32; r += 8)
        hiT[(size_t)(n0 + ty + r) * K + k0 + tx] = __float2half_rn(tile[tx][ty + r]);
}

// ---------------------------------------------------------------------------
extern "C" void kernel_launch(void* const* d_in, const int* in_sizes, int n_in,
                              void* d_out, int out_size)
{
    const float* x      = (const float*)d_in[0];
    const float* w_attn = (const float*)d_in[1];
    const float* b_attn = (const float*)d_in[2];
    const float* w_proj = (const float*)d_in[3];
    const float* b_proj = (const float*)d_in[4];
    float* out = (float*)d_out;

    __half *qkvh, *qkvl, *xh, *xl, *yh, *yl, *wah, *wph;
    cudaGetSymbolAddress((void**)&qkvh, g_qkvh);
    cudaGetSymbolAddress((void**)&qkvl, g_qkvl);
    cudaGetSymbolAddress((void**)&xh, g_xh);
    cudaGetSymbolAddress((void**)&xl, g_xl);
    cudaGetSymbolAddress((void**)&yh, g_yh);
    cudaGetSymbolAddress((void**)&yl, g_yl);
    cudaGetSymbolAddress((void**)&wah, g_wah);
    cudaGetSymbolAddress((void**)&wph, g_wph);

    static bool attr_set = false;
    if (!attr_set) {
        cudaFuncSetAttribute(mma_attn_kernel,
                             cudaFuncAttributeMaxDynamicSharedMemorySize, ATTN_SMEM);
        cudaFuncSetAttribute(mma_gemm_kernel,
                             cudaFuncAttributeMaxDynamicSharedMemorySize, GEMM_SMEM);
        attr_set = true;
    }

    // 0) conversions
    {
        int n4 = (M_ROWS * DMODEL) / 4;
        split_kernel_f16<<<(n4 + 255) / 256, 256>>>(x, xh, xl, n4);
        dim3 blk(32, 8);
        transpose_f16_kernel<<<dim3(QKV_N / 32, DMODEL / 32), blk>>>(w_attn, wah, DMODEL, QKV_N);
        transpose_f16_kernel<<<dim3(DMODEL / 32, DMODEL / 32), blk>>>(w_proj, wph, DMODEL, DMODEL);
    }
    // 1) QKV GEMM (fp16 2-term) -> fp16 hi/lo qkv
    {
        dim3 grid(QKV_N / 128, M_ROWS / 128);
        mma_gemm_kernel<<<grid, 256, GEMM_SMEM>>>(xh, xl, wah, b_attn,
                                                  nullptr, qkvh, qkvl, QKV_N);
    }
    // 2) causal flash attention (fp16 2-term) -> fp16 hi/lo y
    {
        dim3 grid(T_SEQ / 128, BATCH * NH);   // (16, 48)
        mma_attn_kernel<<<grid, 256, ATTN_SMEM>>>(qkvh, qkvl, yh, yl);
    }
    // 3) out projection (fp16 2-term) -> fp32 out
    {
        dim3 grid(DMODEL / 128, M_ROWS / 128);
        mma_gemm_kernel<<<grid, 256, GEMM_SMEM>>>(yh, yl, wph, b_proj,
                                                  out, nullptr, nullptr, DMODEL);
    }
}